// round 9
// baseline (speedup 1.0000x reference)
#include <cuda_runtime.h>
#include <cuda_bf16.h>
#include <cstdint>

#define BB 16
#define SS 128
#define TT 64
#define EE 768
#define HH 1024
#define VV 32000

// ---------------- device scratch (static, no allocation) ----------------
__device__ __nv_bfloat16 g_xbf[BB * SS * EE];        // x bf16
__device__ __nv_bfloat16 g_xprojbf[BB * SS * HH];    // x@Wx + b1, bf16
// fragment-packed weights: uint4 per (ntile16, kchunk16, lane)
__device__ uint4 g_pWx[(HH / 16) * (EE / 16) * 32];
__device__ uint4 g_pWh[(HH / 16) * (HH / 16) * 32];
__device__ uint4 g_pWc0[(4096 / 16) * (2560 / 16) * 32];   // gate-interleaved
__device__ uint4 g_pWc1[(4096 / 16) * (2048 / 16) * 32];   // gate-interleaved
__device__ uint4 g_pWc2[(4096 / 16) * (2048 / 16) * 32];   // gate-interleaved
__device__ uint4 g_pFc[(VV / 16) * (HH / 16) * 32];

// double-buffered activations (parity = t&1)
__device__ __nv_bfloat16 g_A0[2][BB * 2560];  // [emb | ctx | h0]
__device__ __nv_bfloat16 g_A1[2][BB * 2048];  // [h0_new | h1_prev]
__device__ __nv_bfloat16 g_A2[2][BB * 2048];  // [h1_new | h2]
__device__ float         g_c[3 * BB * HH];    // cell states
__device__ float         g_hvp[8 * BB * HH];     // h2@Wh split-K partials
__device__ float         g_part[8 * BB * 4096]; // LSTM gate split-K partials
__device__ int           g_cnt[48];              // per (layer, ntile) epilogue counters

// ---------------- prologue ----------------
__global__ void prolog_cvt_x(const float* __restrict__ x) {
    int i = blockIdx.x * 256 + threadIdx.x;
    if (i < BB * SS * EE) g_xbf[i] = __float2bfloat16(x[i]);
}

__global__ void pack_all(const float* __restrict__ Wx, const float* __restrict__ Wh,
                         const float* __restrict__ Wih0, const float* __restrict__ Whh0,
                         const float* __restrict__ Wih1, const float* __restrict__ Whh1,
                         const float* __restrict__ Wih2, const float* __restrict__ Whh2,
                         const float* __restrict__ fcW) {
    const long long C0 = 98304, C1 = C0 + 131072, C2 = C1 + 1310720,
                    C3 = C2 + 1048576, C4 = C3 + 1048576, C5 = C4 + 4096000;
    long long idx = (long long)blockIdx.x * 256 + threadIdx.x;
    if (idx >= C5) return;
    uint4* dst; const float *s1, *s2 = nullptr;
    int N, K1, K2 = 0, tr, il = 0; long long base;
    if (idx < C0)      { dst = g_pWx;  s1 = Wx;   N = HH;   K1 = EE;   tr = 1; base = 0; }
    else if (idx < C1) { dst = g_pWh;  s1 = Wh;   N = HH;   K1 = HH;   tr = 1; base = C0; }
    else if (idx < C2) { dst = g_pWc0; s1 = Wih0; s2 = Whh0; N = 4096; K1 = 1536; K2 = 1024; tr = 0; il = 1; base = C1; }
    else if (idx < C3) { dst = g_pWc1; s1 = Wih1; s2 = Whh1; N = 4096; K1 = 1024; K2 = 1024; tr = 0; il = 1; base = C2; }
    else if (idx < C4) { dst = g_pWc2; s1 = Wih2; s2 = Whh2; N = 4096; K1 = 1024; K2 = 1024; tr = 0; il = 1; base = C3; }
    else               { dst = g_pFc;  s1 = fcW;  N = VV;   K1 = HH;   tr = 0; base = C4; }
    long long li = idx - base;
    int nch = (K1 + K2) >> 4;
    int lane = (int)(li & 31);
    long long tt = li >> 5;
    int ch = (int)(tt % nch);
    int nt = (int)(tt / nch);
    int g = lane >> 2, tig = lane & 3;
    int k = ch * 16 + tig * 2;
    int r0 = nt * 16 + g, r1 = r0 + 8;
    auto ld = [&](int n, int kk) -> float {
        int nn = il ? ((n & 3) * 1024 + (n >> 2)) : n;  // gate-interleave
        if (kk < K1) return tr ? s1[(long long)kk * N + nn] : s1[(long long)nn * K1 + kk];
        return s2[(long long)nn * HH + (kk - K1)];
    };
    auto p2 = [&](float a, float b) -> unsigned {
        __nv_bfloat162 h = __floats2bfloat162_rn(a, b);
        return *reinterpret_cast<unsigned*>(&h);
    };
    uint4 v;
    v.x = p2(ld(r0, k), ld(r0, k + 1));
    v.y = p2(ld(r0, k + 8), ld(r0, k + 9));
    v.z = p2(ld(r1, k), ld(r1, k + 1));
    v.w = p2(ld(r1, k + 8), ld(r1, k + 9));
    dst[li] = v;
}

__global__ void prolog_zero() {
    int i = blockIdx.x * 256 + threadIdx.x;  // 16384 threads
    if (i < BB * HH) {
        g_c[i] = 0.f; g_c[BB * HH + i] = 0.f; g_c[2 * BB * HH + i] = 0.f;
        int b = i >> 10, j = i & 1023;
        __nv_bfloat16 z = __float2bfloat16(0.f);
        g_A0[0][b * 2560 + 1536 + j] = z; g_A0[1][b * 2560 + 1536 + j] = z;
        g_A1[0][b * 2048 + 1024 + j] = z; g_A1[1][b * 2048 + 1024 + j] = z;
        g_A2[0][b * 2048 + 1024 + j] = z; g_A2[1][b * 2048 + 1024 + j] = z;
    }
    if (i < 48) g_cnt[i] = 0;
}

// ---------------- GEMM v5: packed-B, smem A, optional fused LSTM cell ----------------
__device__ __forceinline__ void mma16816(float c[4], uint32_t a0, uint32_t a1, uint32_t a2,
                                         uint32_t a3, uint32_t b0, uint32_t b1) {
    asm volatile(
        "mma.sync.aligned.m16n8k16.row.col.f32.bf16.bf16.f32 "
        "{%0,%1,%2,%3}, {%4,%5,%6,%7}, {%8,%9}, {%0,%1,%2,%3};\n"
        : "+f"(c[0]), "+f"(c[1]), "+f"(c[2]), "+f"(c[3])
        : "r"(a0), "r"(a1), "r"(a2), "r"(a3), "r"(b0), "r"(b1));
}

#define APAD 8
#define AMAXC (64 * 16)

// cMode: 0 = bf16 out (Cb), 1 = fp32 out (Cf + z*partStride), 2 = fp32 partials + fused cell
template <bool EF>
__global__ __launch_bounds__(256) void gemm_v5(
    const __nv_bfloat16* __restrict__ A, int lda,
    const uint4* __restrict__ B, int nchTot,
    int cMode, float* Cf, __nv_bfloat16* Cb, long long ldc, int partStride,
    const float* __restrict__ bias, int nCh,
    const float* __restrict__ bih, const float* __restrict__ bhh,
    int cntBase, __nv_bfloat16* hOut1, int st1, __nv_bfloat16* hOut2, int st2,
    float* cState) {
    __shared__ __nv_bfloat16 s_a[16][AMAXC + APAD];
    int w = threadIdx.x >> 5, lane = threadIdx.x & 31;
    int g = lane >> 2, tig = lane & 3;
    int m0 = blockIdx.y * 16;
    int n0 = blockIdx.x * 256 + w * 32;
    int ch0 = blockIdx.z * nCh;

    {  // stage A slice (16 x nCh*16), coalesced uint4
        int cols4 = nCh * 2;
        for (int idx = threadIdx.x; idx < 16 * cols4; idx += 256) {
            int r = idx / cols4, cc = idx % cols4;
            uint4 v = *reinterpret_cast<const uint4*>(
                A + (long long)(m0 + r) * lda + ch0 * 16 + cc * 8);
            *reinterpret_cast<uint4*>(&s_a[r][cc * 8]) = v;
        }
    }
    __syncthreads();

    const uint4* bp0 = B + ((long long)(n0 >> 4) * nchTot + ch0) * 32 + lane;
    const uint4* bp1 = bp0 + (long long)nchTot * 32;
    uint32_t sab = (uint32_t)__cvta_generic_to_shared(&s_a[lane & 15][(lane >> 4) * 8]);

    float acc[4][4] = {{0.f}, {0.f}, {0.f}, {0.f}};
#pragma unroll 4
    for (int c = 0; c < nCh; c++) {
        uint4 b0 = EF ? __ldcs(bp0 + (long long)c * 32) : __ldg(bp0 + (long long)c * 32);
        uint4 b1 = EF ? __ldcs(bp1 + (long long)c * 32) : __ldg(bp1 + (long long)c * 32);
        uint32_t a0, a1, a2, a3;
        asm volatile("ldmatrix.sync.aligned.m8n8.x4.shared.b16 {%0,%1,%2,%3}, [%4];"
                     : "=r"(a0), "=r"(a1), "=r"(a2), "=r"(a3)
                     : "r"(sab + (uint32_t)c * 32));
        mma16816(acc[0], a0, a1, a2, a3, b0.x, b0.y);
        mma16816(acc[1], a0, a1, a2, a3, b0.z, b0.w);
        mma16816(acc[2], a0, a1, a2, a3, b1.x, b1.y);
        mma16816(acc[3], a0, a1, a2, a3, b1.z, b1.w);
    }

    int r0 = m0 + g, r1 = m0 + g + 8;
    if (cMode == 0) {
#pragma unroll
        for (int q = 0; q < 4; q++) {
            int col = n0 + q * 8 + tig * 2;
            float bv0 = bias[col], bv1 = bias[col + 1];
            Cb[(long long)r0 * ldc + col]     = __float2bfloat16(acc[q][0] + bv0);
            Cb[(long long)r0 * ldc + col + 1] = __float2bfloat16(acc[q][1] + bv1);
            Cb[(long long)r1 * ldc + col]     = __float2bfloat16(acc[q][2] + bv0);
            Cb[(long long)r1 * ldc + col + 1] = __float2bfloat16(acc[q][3] + bv1);
        }
        return;
    }
    float* C = Cf + (long long)blockIdx.z * partStride;
#pragma unroll
    for (int q = 0; q < 4; q++) {
        int col = n0 + q * 8 + tig * 2;
        float bv0 = bias ? bias[col] : 0.f, bv1 = bias ? bias[col + 1] : 0.f;
        C[(long long)r0 * ldc + col]     = acc[q][0] + bv0;
        C[(long long)r0 * ldc + col + 1] = acc[q][1] + bv1;
        C[(long long)r1 * ldc + col]     = acc[q][2] + bv0;
        C[(long long)r1 * ldc + col + 1] = acc[q][3] + bv1;
    }
    if (cMode != 2) return;

    // ---- fused LSTM cell: last z-block of this n-tile does the epilogue ----
    __threadfence();
    __shared__ int s_last;
    if (threadIdx.x == 0)
        s_last = (atomicAdd(&g_cnt[cntBase + blockIdx.x], 1) == (int)gridDim.z - 1);
    __syncthreads();
    if (!s_last) return;
    int nt = blockIdx.x;
#pragma unroll
    for (int e = 0; e < 4; e++) {
        int idx = threadIdx.x + e * 256;  // 0..1023 = 16 batch x 64 units
        int b = idx >> 6, jj = idx & 63;
        int j = nt * 64 + jj;
        float gi = bih[j] + bhh[j];
        float gf = bih[1024 + j] + bhh[1024 + j];
        float gg = bih[2048 + j] + bhh[2048 + j];
        float go = bih[3072 + j] + bhh[3072 + j];
        const float* base = g_part + b * 4096 + nt * 256 + jj * 4;
#pragma unroll
        for (int z = 0; z < 8; z++) {
            float4 p = *reinterpret_cast<const float4*>(base + (long long)z * (BB * 4096));
            gi += p.x; gf += p.y; gg += p.z; go += p.w;
        }
        float si = 1.f / (1.f + expf(-gi));
        float sf = 1.f / (1.f + expf(-gf));
        float so = 1.f / (1.f + expf(-go));
        float* cc = cState + b * HH + j;
        float cn = sf * (*cc) + si * tanhf(gg);
        *cc = cn;
        __nv_bfloat16 hb = __float2bfloat16(so * tanhf(cn));
        if (hOut1) hOut1[b * st1 + j] = hb;
        hOut2[b * st2 + j] = hb;
    }
    if (threadIdx.x == 0) atomicExch(&g_cnt[cntBase + blockIdx.x], 0);
}

// ---------------- fused attention (reads hv partials, writes emb|ctx) ----------------
__global__ __launch_bounds__(1024) void attn_fused(
    const float* __restrict__ w2, const float* __restrict__ b2,
    const int* __restrict__ tseq, const float* __restrict__ emb, int t,
    __nv_bfloat16* __restrict__ A0w) {
    __shared__ float hv_s[HH];
    __shared__ float w2_s[HH];
    __shared__ float sc[SS];
    __shared__ float bc;
    int b = blockIdx.x, tid = threadIdx.x;
    {
        float s = 0.f;
#pragma unroll
        for (int p = 0; p < 8; p++) s += g_hvp[p * BB * HH + b * HH + tid];
        hv_s[tid] = s;
        w2_s[tid] = w2[tid];
    }
    __syncthreads();
    int w = tid >> 5, lane = tid & 31;
#pragma unroll
    for (int rr = 0; rr < 4; rr++) {
        int s = w + rr * 32;
        const __nv_bfloat16* row = g_xprojbf + ((long long)b * SS + s) * HH;
        float sum = 0.f;
#pragma unroll
        for (int it = 0; it < 4; it++) {
            int k0 = it * 256 + lane * 8;
            uint4 v = *reinterpret_cast<const uint4*>(row + k0);
            const __nv_bfloat162* hp = reinterpret_cast<const __nv_bfloat162*>(&v);
#pragma unroll
            for (int j = 0; j < 4; j++) {
                float2 f = __bfloat1622float2(hp[j]);
                int k = k0 + j * 2;
                float a = f.x + hv_s[k];
                float c = f.y + hv_s[k + 1];
                sum += (a > 0.f ? a * w2_s[k] : 0.f) + (c > 0.f ? c * w2_s[k + 1] : 0.f);
            }
        }
#pragma unroll
        for (int o = 16; o; o >>= 1) sum += __shfl_xor_sync(0xffffffffu, sum, o);
        if (!lane) sc[s] = sum + b2[0];
    }
    __syncthreads();
    if (w == 0) {
        float m = -1e30f;
#pragma unroll
        for (int i = 0; i < 4; i++) m = fmaxf(m, sc[lane + i * 32]);
#pragma unroll
        for (int o = 16; o; o >>= 1) m = fmaxf(m, __shfl_xor_sync(0xffffffffu, m, o));
        float su = 0.f;
#pragma unroll
        for (int i = 0; i < 4; i++) su += expf(sc[lane + i * 32] - m);
#pragma unroll
        for (int o = 16; o; o >>= 1) su += __shfl_xor_sync(0xffffffffu, su, o);
        if (!lane) bc = m + logf(su);
    }
    __syncthreads();
    float lse = bc;
    if (tid < SS) sc[tid] -= lse;
    __syncthreads();
    if (tid < EE) {
        const __nv_bfloat16* xb = g_xbf + (long long)b * SS * EE + tid;
        float acc = 0.f;
#pragma unroll 8
        for (int s = 0; s < SS; s++) acc += sc[s] * __bfloat162float(xb[(long long)s * EE]);
        A0w[b * 2560 + EE + tid] = __float2bfloat16(acc);
        int tok = tseq[b * TT + t];
        A0w[b * 2560 + tid] = __float2bfloat16(emb[(long long)tok * EE + tid]);
    }
}

// ---------------- in-place log_softmax over V (float4) ----------------
__global__ __launch_bounds__(1024) void lsm_kernel(float* __restrict__ dout, int t) {
    float4* row = reinterpret_cast<float4*>(dout + (long long)blockIdx.x * TT * VV +
                                            (long long)t * VV);
    const int NV4 = VV / 4;
    __shared__ float sm[32];
    __shared__ float bc;
    int tid = threadIdx.x, lane = tid & 31, wid = tid >> 5;
    float m = -1e30f;
    for (int i = tid; i < NV4; i += 1024) {
        float4 v = row[i];
        m = fmaxf(m, fmaxf(fmaxf(v.x, v.y), fmaxf(v.z, v.w)));
    }
#pragma unroll
    for (int o = 16; o; o >>= 1) m = fmaxf(m, __shfl_xor_sync(0xffffffffu, m, o));
    if (!lane) sm[wid] = m;
    __syncthreads();
    if (tid < 32) {
        float mm = sm[tid];
#pragma unroll
        for (int o = 16; o; o >>= 1) mm = fmaxf(mm, __shfl_xor_sync(0xffffffffu, mm, o));
        if (!tid) bc = mm;
    }
    __syncthreads();
    m = bc;
    float s = 0.f;
    for (int i = tid; i < NV4; i += 1024) {
        float4 v = row[i];
        s += expf(v.x - m) + expf(v.y - m) + expf(v.z - m) + expf(v.w - m);
    }
#pragma unroll
    for (int o = 16; o; o >>= 1) s += __shfl_xor_sync(0xffffffffu, s, o);
    __syncthreads();
    if (!lane) sm[wid] = s;
    __syncthreads();
    if (tid < 32) {
        float ss = sm[tid];
#pragma unroll
        for (int o = 16; o; o >>= 1) ss += __shfl_xor_sync(0xffffffffu, ss, o);
        if (!tid) bc = m + logf(ss);
    }
    __syncthreads();
    float lse = bc;
    for (int i = tid; i < NV4; i += 1024) {
        float4 v = row[i];
        v.x -= lse; v.y -= lse; v.z -= lse; v.w -= lse;
        row[i] = v;
    }
}

// ---------------- host launch ----------------
extern "C" void kernel_launch(void* const* d_in, const int* in_sizes, int n_in,
                              void* d_out, int out_size) {
    const float* x    = (const float*)d_in[0];
    const int*   tseq = (const int*)d_in[1];
    const float* emb  = (const float*)d_in[2];
    const float* Wx   = (const float*)d_in[3];
    const float* Wh   = (const float*)d_in[4];
    const float* b1   = (const float*)d_in[5];
    const float* w2   = (const float*)d_in[6];
    const float* b2   = (const float*)d_in[7];
    const float* fcW  = (const float*)d_in[8];
    const float* fcb  = (const float*)d_in[9];
    const float* Wih0 = (const float*)d_in[10];
    const float* Whh0 = (const float*)d_in[11];
    const float* bih0 = (const float*)d_in[12];
    const float* bhh0 = (const float*)d_in[13];
    const float* Wih1 = (const float*)d_in[14];
    const float* Whh1 = (const float*)d_in[15];
    const float* bih1 = (const float*)d_in[16];
    const float* bhh1 = (const float*)d_in[17];
    const float* Wih2 = (const float*)d_in[18];
    const float* Whh2 = (const float*)d_in[19];
    const float* bih2 = (const float*)d_in[20];
    const float* bhh2 = (const float*)d_in[21];
    float* dout = (float*)d_out;

    static cudaStream_t s2 = nullptr;
    static cudaEvent_t evA = nullptr, evB0 = nullptr, evB1 = nullptr, evEnd = nullptr;
    static __nv_bfloat16 *pA0[2], *pA1[2], *pA2[2], *pXp;
    static uint4 *pWx_, *pWh_, *pWc0_, *pWc1_, *pWc2_, *pFc_;
    static float *pHvp, *pPart, *pC;
    if (!s2) {
        cudaStreamCreateWithFlags(&s2, cudaStreamNonBlocking);
        cudaEventCreateWithFlags(&evA, cudaEventDisableTiming);
        cudaEventCreateWithFlags(&evB0, cudaEventDisableTiming);
        cudaEventCreateWithFlags(&evB1, cudaEventDisableTiming);
        cudaEventCreateWithFlags(&evEnd, cudaEventDisableTiming);
        void* p;
        cudaGetSymbolAddress(&p, g_A0);  pA0[0] = (__nv_bfloat16*)p; pA0[1] = pA0[0] + BB * 2560;
        cudaGetSymbolAddress(&p, g_A1);  pA1[0] = (__nv_bfloat16*)p; pA1[1] = pA1[0] + BB * 2048;
        cudaGetSymbolAddress(&p, g_A2);  pA2[0] = (__nv_bfloat16*)p; pA2[1] = pA2[0] + BB * 2048;
        cudaGetSymbolAddress(&p, g_xprojbf); pXp = (__nv_bfloat16*)p;
        cudaGetSymbolAddress(&p, g_pWx);  pWx_ = (uint4*)p;
        cudaGetSymbolAddress(&p, g_pWh);  pWh_ = (uint4*)p;
        cudaGetSymbolAddress(&p, g_pWc0); pWc0_ = (uint4*)p;
        cudaGetSymbolAddress(&p, g_pWc1); pWc1_ = (uint4*)p;
        cudaGetSymbolAddress(&p, g_pWc2); pWc2_ = (uint4*)p;
        cudaGetSymbolAddress(&p, g_pFc);  pFc_ = (uint4*)p;
        cudaGetSymbolAddress(&p, g_hvp);  pHvp = (float*)p;
        cudaGetSymbolAddress(&p, g_part); pPart = (float*)p;
        cudaGetSymbolAddress(&p, g_c);    pC = (float*)p;
    }
    static __nv_bfloat16* pXbf = nullptr;
    if (!pXbf) { void* p; cudaGetSymbolAddress(&p, g_xbf); pXbf = (__nv_bfloat16*)p; }

    // -------- prologue --------
    prolog_cvt_x<<<(BB * SS * EE + 255) / 256, 256>>>(x);
    pack_all<<<30208, 256>>>(Wx, Wh, Wih0, Whh0, Wih1, Whh1, Wih2, Whh2, fcW);
    prolog_zero<<<64, 256>>>();
    // x_proj: M=2048, N=1024, K=768 (48 chunks), bf16 out
    gemm_v5<false><<<dim3(4, 128, 1), 256>>>(pXbf, EE, pWx_, EE / 16, 0, nullptr, pXp,
                                             HH, 0, b1, 48, nullptr, nullptr, 0,
                                             nullptr, 0, nullptr, 0, nullptr);

    // -------- time loop --------
    for (int t = 0; t < TT; t++) {
        int par = t & 1;
        // hv = h2 @ Wh : split-K=8 partials
        gemm_v5<false><<<dim3(4, 1, 8), 256>>>(pA2[par] + 1024, 2048, pWh_, HH / 16, 1,
                                               pHvp, nullptr, HH, BB * HH, nullptr, 8,
                                               nullptr, nullptr, 0, nullptr, 0, nullptr,
                                               0, nullptr);
        attn_fused<<<BB, 1024>>>(w2, b2, tseq, emb, t, pA0[par]);
        // layer 0 (+fused cell): K=2560, split-K=8
        gemm_v5<false><<<dim3(16, 1, 8), 256>>>(pA0[par], 2560, pWc0_, 2560 / 16, 2,
                                                pPart, nullptr, 4096, BB * 4096, nullptr,
                                                20, bih0, bhh0, 0,
                                                pA1[par], 2048, pA0[par ^ 1] + 1536, 2560,
                                                pC);
        // layer 1
        gemm_v5<false><<<dim3(16, 1, 8), 256>>>(pA1[par], 2048, pWc1_, 2048 / 16, 2,
                                                pPart, nullptr, 4096, BB * 4096, nullptr,
                                                16, bih1, bhh1, 16,
                                                pA2[par], 2048, pA1[par ^ 1] + 1024, 2048,
                                                pC + BB * HH);
        // layer 2: epilogue writes h2 -> A2[par^1]; fc(t-2) read that slice
        if (t >= 2) cudaStreamWaitEvent(0, par ? evB1 : evB0, 0);
        gemm_v5<false><<<dim3(16, 1, 8), 256>>>(pA2[par], 2048, pWc2_, 2048 / 16, 2,
                                                pPart, nullptr, 4096, BB * 4096, nullptr,
                                                16, bih2, bhh2, 32,
                                                nullptr, 0, pA2[par ^ 1] + 1024, 2048,
                                                pC + 2 * BB * HH);
        // fork fc + lsm onto side stream
        cudaEventRecord(evA, 0);
        cudaStreamWaitEvent(s2, evA, 0);
        gemm_v5<true><<<dim3(125, 1, 1), 256, 0, s2>>>(pA2[par ^ 1] + 1024, 2048, pFc_,
                                                       HH / 16, 1,
                                                       dout + (long long)t * VV, nullptr,
                                                       (long long)TT * VV, 0, fcb, 64,
                                                       nullptr, nullptr, 0, nullptr, 0,
                                                       nullptr, 0, nullptr);
        cudaEventRecord(par ? evB1 : evB0, s2);
        lsm_kernel<<<BB, 1024, 0, s2>>>(dout, t);
    }
    cudaEventRecord(evEnd, s2);
    cudaStreamWaitEvent(0, evEnd, 0);
}

// round 11
// speedup vs baseline: 1.1115x; 1.1115x over previous
#include <cuda_runtime.h>
#include <cuda_bf16.h>
#include <cstdint>

#define BB 16
#define SS 128
#define TT 64
#define EE 768
#define HH 1024
#define VV 32000

// ---------------- device scratch (static, no allocation) ----------------
__device__ __nv_bfloat16 g_xbf[BB * SS * EE];        // x bf16
__device__ __nv_bfloat16 g_xprojbf[BB * SS * HH];    // x@Wx + b1, bf16
// fragment-packed weights: uint4 per (ntile16, kchunk16, lane)
__device__ uint4 g_pWx[(HH / 16) * (EE / 16) * 32];
__device__ uint4 g_pWh[(HH / 16) * (HH / 16) * 32];
__device__ uint4 g_pWc0[(4096 / 16) * (2560 / 16) * 32];
__device__ uint4 g_pWc1[(4096 / 16) * (2048 / 16) * 32];
__device__ uint4 g_pWc2[(4096 / 16) * (2048 / 16) * 32];
__device__ uint4 g_pFc[(VV / 16) * (HH / 16) * 32];

__device__ __nv_bfloat16 g_A0[BB * 2560];   // [emb | ctx | h0]
__device__ __nv_bfloat16 g_A1[BB * 2048];   // [h0_new | h1_prev]
__device__ __nv_bfloat16 g_A2[BB * 2048];   // [h1_new | h2]
__device__ float         g_c[3 * BB * HH];  // cell states
__device__ float         g_hvp[8 * BB * HH];     // h2@Wh split-K partials
__device__ float         g_part[8 * BB * 4096]; // LSTM gate split-K partials

// ---------------- single combined prologue (pack + cvt_x + zero) ----------------
__global__ void prolog_combined(
    const float* __restrict__ Wx, const float* __restrict__ Wh,
    const float* __restrict__ Wih0, const float* __restrict__ Whh0,
    const float* __restrict__ Wih1, const float* __restrict__ Whh1,
    const float* __restrict__ Wih2, const float* __restrict__ Whh2,
    const float* __restrict__ fcW, const float* __restrict__ x) {
    const long long C0 = 98304, C1 = C0 + 131072, C2 = C1 + 1310720,
                    C3 = C2 + 1048576, C4 = C3 + 1048576, C5 = C4 + 4096000;
    long long idx = (long long)blockIdx.x * 256 + threadIdx.x;
    if (idx < C5) {
        uint4* dst; const float *s1, *s2 = nullptr;
        int N, K1, K2 = 0, tr; long long base;
        if (idx < C0)      { dst = g_pWx;  s1 = Wx;   N = HH;   K1 = EE;   tr = 1; base = 0; }
        else if (idx < C1) { dst = g_pWh;  s1 = Wh;   N = HH;   K1 = HH;   tr = 1; base = C0; }
        else if (idx < C2) { dst = g_pWc0; s1 = Wih0; s2 = Whh0; N = 4096; K1 = 1536; K2 = 1024; tr = 0; base = C1; }
        else if (idx < C3) { dst = g_pWc1; s1 = Wih1; s2 = Whh1; N = 4096; K1 = 1024; K2 = 1024; tr = 0; base = C2; }
        else if (idx < C4) { dst = g_pWc2; s1 = Wih2; s2 = Whh2; N = 4096; K1 = 1024; K2 = 1024; tr = 0; base = C3; }
        else               { dst = g_pFc;  s1 = fcW;  N = VV;   K1 = HH;   tr = 0; base = C4; }
        long long li = idx - base;
        int nch = (K1 + K2) >> 4;
        int lane = (int)(li & 31);
        long long tt = li >> 5;
        int ch = (int)(tt % nch);
        int nt = (int)(tt / nch);
        int g = lane >> 2, tig = lane & 3;
        int k = ch * 16 + tig * 2;
        int r0 = nt * 16 + g, r1 = r0 + 8;
        auto ld = [&](int n, int kk) -> float {
            if (kk < K1) return tr ? s1[(long long)kk * N + n] : s1[(long long)n * K1 + kk];
            return s2[(long long)n * HH + (kk - K1)];
        };
        auto p2 = [&](float a, float b) -> unsigned {
            __nv_bfloat162 h = __floats2bfloat162_rn(a, b);
            return *reinterpret_cast<unsigned*>(&h);
        };
        uint4 v;
        v.x = p2(ld(r0, k), ld(r0, k + 1));
        v.y = p2(ld(r0, k + 8), ld(r0, k + 9));
        v.z = p2(ld(r1, k), ld(r1, k + 1));
        v.w = p2(ld(r1, k + 8), ld(r1, k + 9));
        dst[li] = v;
        return;
    }
    long long r = idx - C5;
    if (r < (long long)BB * SS * EE) {  // x -> bf16
        g_xbf[r] = __float2bfloat16(x[r]);
        return;
    }
    r -= (long long)BB * SS * EE;
    if (r < 3 * BB * HH) {  // zero state + h slots
        g_c[r] = 0.f;
        __nv_bfloat16 z = __float2bfloat16(0.f);
        if (r < BB * HH) {
            int b = (int)(r >> 10), j = (int)(r & 1023);
            g_A0[b * 2560 + 1536 + j] = z;
        }
        if (r < BB * 2048) { g_A1[r] = z; g_A2[r] = z; }
    }
}

// ---------------- 16xN bf16 tensor-core GEMM (R8 gemm_v4, unroll 8) ----------------
__device__ __forceinline__ const __nv_bfloat16* selA(int t) {
    switch (t) {
        case 0: return g_xbf;
        case 1: return g_A0;
        case 2: return g_A1;
        case 3: return g_A2;
        default: return g_A2 + 1024;  // h2 slice
    }
}

__device__ __forceinline__ void mma16816(float c[4], uint32_t a0, uint32_t a1, uint32_t a2,
                                         uint32_t a3, uint32_t b0, uint32_t b1) {
    asm volatile(
        "mma.sync.aligned.m16n8k16.row.col.f32.bf16.bf16.f32 "
        "{%0,%1,%2,%3}, {%4,%5,%6,%7}, {%8,%9}, {%0,%1,%2,%3};\n"
        : "+f"(c[0]), "+f"(c[1]), "+f"(c[2]), "+f"(c[3])
        : "r"(a0), "r"(a1), "r"(a2), "r"(a3), "r"(b0), "r"(b1));
}

#define APAD 8
#define AMAXC (64 * 16)

// cTag: 0 = g_xprojbf (bf16), 1 = g_hvp, 2 = g_part, 3 = external fp32 (dout)
template <bool EF>
__global__ __launch_bounds__(256) void gemm_v4(
    int aTag, int lda, int bTag, int cTag, float* cExt, long long ldc,
    int partStride, const float* __restrict__ bias, int nCh) {
    __shared__ __nv_bfloat16 s_a[16][AMAXC + APAD];
    const __nv_bfloat16* A = selA(aTag);
    const uint4* B;
    int nchTot;
    switch (bTag) {
        case 0: B = g_pWx;  nchTot = EE / 16;   break;
        case 1: B = g_pWh;  nchTot = HH / 16;   break;
        case 2: B = g_pWc0; nchTot = 2560 / 16; break;
        case 3: B = g_pWc1; nchTot = 2048 / 16; break;
        case 4: B = g_pWc2; nchTot = 2048 / 16; break;
        default: B = g_pFc; nchTot = HH / 16;   break;
    }
    int w = threadIdx.x >> 5, lane = threadIdx.x & 31;
    int g = lane >> 2, tig = lane & 3;
    int m0 = blockIdx.y * 16;
    int n0 = blockIdx.x * 256 + w * 32;
    int ch0 = blockIdx.z * nCh;

    // ---- stage A slice (16 x nCh*16) into padded smem, coalesced uint4 ----
    {
        int cols4 = nCh * 2;
        for (int idx = threadIdx.x; idx < 16 * cols4; idx += 256) {
            int r = idx / cols4, cc = idx % cols4;
            uint4 v = *reinterpret_cast<const uint4*>(
                A + (long long)(m0 + r) * lda + ch0 * 16 + cc * 8);
            *reinterpret_cast<uint4*>(&s_a[r][cc * 8]) = v;
        }
    }
    __syncthreads();

    const uint4* bp0 = B + ((long long)(n0 >> 4) * nchTot + ch0) * 32 + lane;
    const uint4* bp1 = bp0 + (long long)nchTot * 32;
    uint32_t sab = (uint32_t)__cvta_generic_to_shared(&s_a[lane & 15][(lane >> 4) * 8]);

    float acc[4][4] = {{0.f}, {0.f}, {0.f}, {0.f}};
#pragma unroll 8
    for (int c = 0; c < nCh; c++) {
        uint4 b0 = EF ? __ldcs(bp0 + (long long)c * 32) : __ldg(bp0 + (long long)c * 32);
        uint4 b1 = EF ? __ldcs(bp1 + (long long)c * 32) : __ldg(bp1 + (long long)c * 32);
        uint32_t a0, a1, a2, a3;
        asm volatile("ldmatrix.sync.aligned.m8n8.x4.shared.b16 {%0,%1,%2,%3}, [%4];"
                     : "=r"(a0), "=r"(a1), "=r"(a2), "=r"(a3)
                     : "r"(sab + (uint32_t)c * 32));
        mma16816(acc[0], a0, a1, a2, a3, b0.x, b0.y);
        mma16816(acc[1], a0, a1, a2, a3, b0.z, b0.w);
        mma16816(acc[2], a0, a1, a2, a3, b1.x, b1.y);
        mma16816(acc[3], a0, a1, a2, a3, b1.z, b1.w);
    }

    int r0 = m0 + g, r1 = m0 + g + 8;
    if (cTag == 0) {
        __nv_bfloat16* Cb = g_xprojbf;
#pragma unroll
        for (int q = 0; q < 4; q++) {
            int col = n0 + q * 8 + tig * 2;
            float bv0 = bias[col], bv1 = bias[col + 1];
            Cb[(long long)r0 * ldc + col]     = __float2bfloat16(acc[q][0] + bv0);
            Cb[(long long)r0 * ldc + col + 1] = __float2bfloat16(acc[q][1] + bv1);
            Cb[(long long)r1 * ldc + col]     = __float2bfloat16(acc[q][2] + bv0);
            Cb[(long long)r1 * ldc + col + 1] = __float2bfloat16(acc[q][3] + bv1);
        }
        return;
    }
    float* C = (cTag == 1) ? g_hvp : (cTag == 2) ? g_part : cExt;
    C += (long long)blockIdx.z * partStride;
#pragma unroll
    for (int q = 0; q < 4; q++) {
        int col = n0 + q * 8 + tig * 2;
        float bv0 = bias ? bias[col] : 0.f, bv1 = bias ? bias[col + 1] : 0.f;
        C[(long long)r0 * ldc + col]     = acc[q][0] + bv0;
        C[(long long)r0 * ldc + col + 1] = acc[q][1] + bv1;
        C[(long long)r1 * ldc + col]     = acc[q][2] + bv0;
        C[(long long)r1 * ldc + col + 1] = acc[q][3] + bv1;
    }
}

// ---------------- fused attention (R8 version) ----------------
__global__ __launch_bounds__(1024) void attn_fused(
    const float* __restrict__ w2, const float* __restrict__ b2,
    const int* __restrict__ tseq, const float* __restrict__ emb, int t) {
    __shared__ float hv_s[HH];
    __shared__ float w2_s[HH];
    __shared__ float sc[SS];
    __shared__ float bc;
    int b = blockIdx.x, tid = threadIdx.x;
    {
        float s = 0.f;
#pragma unroll
        for (int p = 0; p < 8; p++) s += g_hvp[p * BB * HH + b * HH + tid];
        hv_s[tid] = s;
        w2_s[tid] = w2[tid];
    }
    __syncthreads();
    int w = tid >> 5, lane = tid & 31;
#pragma unroll
    for (int rr = 0; rr < 4; rr++) {
        int s = w + rr * 32;
        const __nv_bfloat16* row = g_xprojbf + ((long long)b * SS + s) * HH;
        float sum = 0.f;
#pragma unroll
        for (int it = 0; it < 4; it++) {
            int k0 = it * 256 + lane * 8;
            uint4 v = *reinterpret_cast<const uint4*>(row + k0);
            const __nv_bfloat162* hp = reinterpret_cast<const __nv_bfloat162*>(&v);
#pragma unroll
            for (int j = 0; j < 4; j++) {
                float2 f = __bfloat1622float2(hp[j]);
                int k = k0 + j * 2;
                float a = f.x + hv_s[k];
                float c = f.y + hv_s[k + 1];
                sum += (a > 0.f ? a * w2_s[k] : 0.f) + (c > 0.f ? c * w2_s[k + 1] : 0.f);
            }
        }
#pragma unroll
        for (int o = 16; o; o >>= 1) sum += __shfl_xor_sync(0xffffffffu, sum, o);
        if (!lane) sc[s] = sum + b2[0];
    }
    __syncthreads();
    if (w == 0) {
        float m = -1e30f;
#pragma unroll
        for (int i = 0; i < 4; i++) m = fmaxf(m, sc[lane + i * 32]);
#pragma unroll
        for (int o = 16; o; o >>= 1) m = fmaxf(m, __shfl_xor_sync(0xffffffffu, m, o));
        float su = 0.f;
#pragma unroll
        for (int i = 0; i < 4; i++) su += expf(sc[lane + i * 32] - m);
#pragma unroll
        for (int o = 16; o; o >>= 1) su += __shfl_xor_sync(0xffffffffu, su, o);
        if (!lane) bc = m + logf(su);
    }
    __syncthreads();
    float lse = bc;
    if (tid < SS) sc[tid] -= lse;
    __syncthreads();
    if (tid < EE) {
        const __nv_bfloat16* xb = g_xbf + (long long)b * SS * EE + tid;
        float acc = 0.f;
#pragma unroll 8
        for (int s = 0; s < SS; s++) acc += sc[s] * __bfloat162float(xb[(long long)s * EE]);
        g_A0[b * 2560 + EE + tid] = __float2bfloat16(acc);
        int tok = tseq[b * TT + t];
        g_A0[b * 2560 + tid] = __float2bfloat16(emb[(long long)tok * EE + tid]);
    }
}

// ---------------- LSTM cell elementwise (sums 8 split-K partials) ----------------
__global__ __launch_bounds__(256) void lstm_cell(
    const float* __restrict__ bih, const float* __restrict__ bhh, int layer) {
    int idx = blockIdx.x * 256 + threadIdx.x;  // 16384
    int b = idx >> 10, j = idx & 1023;
    float gi = bih[j] + bhh[j];
    float gf = bih[1024 + j] + bhh[1024 + j];
    float gg = bih[2048 + j] + bhh[2048 + j];
    float go = bih[3072 + j] + bhh[3072 + j];
#pragma unroll
    for (int p = 0; p < 8; p++) {
        const float* pp = g_part + p * (BB * 4096) + b * 4096;
        gi += pp[j];
        gf += pp[1024 + j];
        gg += pp[2048 + j];
        go += pp[3072 + j];
    }
    float si = 1.f / (1.f + expf(-gi));
    float sf = 1.f / (1.f + expf(-gf));
    float so = 1.f / (1.f + expf(-go));
    float* cc = g_c + layer * (BB * HH) + idx;
    float cn = sf * (*cc) + si * tanhf(gg);
    *cc = cn;
    float h = so * tanhf(cn);
    __nv_bfloat16 hb = __float2bfloat16(h);
    if (layer == 0) {
        g_A1[b * 2048 + j] = hb;
        g_A0[b * 2560 + 1536 + j] = hb;
    } else if (layer == 1) {
        g_A2[b * 2048 + j] = hb;
        g_A1[b * 2048 + 1024 + j] = hb;
    } else {
        g_A2[b * 2048 + 1024 + j] = hb;
    }
}

// ---------------- in-place log_softmax over V (float4) ----------------
__global__ __launch_bounds__(1024) void lsm_kernel(float* __restrict__ dout, int t) {
    float4* row = reinterpret_cast<float4*>(dout + (long long)blockIdx.x * TT * VV +
                                            (long long)t * VV);
    const int NV4 = VV / 4;
    __shared__ float sm[32];
    __shared__ float bc;
    int tid = threadIdx.x, lane = tid & 31, wid = tid >> 5;
    float m = -1e30f;
    for (int i = tid; i < NV4; i += 1024) {
        float4 v = row[i];
        m = fmaxf(m, fmaxf(fmaxf(v.x, v.y), fmaxf(v.z, v.w)));
    }
#pragma unroll
    for (int o = 16; o; o >>= 1) m = fmaxf(m, __shfl_xor_sync(0xffffffffu, m, o));
    if (!lane) sm[wid] = m;
    __syncthreads();
    if (tid < 32) {
        float mm = sm[tid];
#pragma unroll
        for (int o = 16; o; o >>= 1) mm = fmaxf(mm, __shfl_xor_sync(0xffffffffu, mm, o));
        if (!tid) bc = mm;
    }
    __syncthreads();
    m = bc;
    float s = 0.f;
    for (int i = tid; i < NV4; i += 1024) {
        float4 v = row[i];
        s += expf(v.x - m) + expf(v.y - m) + expf(v.z - m) + expf(v.w - m);
    }
#pragma unroll
    for (int o = 16; o; o >>= 1) s += __shfl_xor_sync(0xffffffffu, s, o);
    __syncthreads();
    if (!lane) sm[wid] = s;
    __syncthreads();
    if (tid < 32) {
        float ss = sm[tid];
#pragma unroll
        for (int o = 16; o; o >>= 1) ss += __shfl_xor_sync(0xffffffffu, ss, o);
        if (!tid) bc = m + logf(ss);
    }
    __syncthreads();
    float lse = bc;
    for (int i = tid; i < NV4; i += 1024) {
        float4 v = row[i];
        v.x -= lse; v.y -= lse; v.z -= lse; v.w -= lse;
        row[i] = v;
    }
}

// ---------------- host launch ----------------
extern "C" void kernel_launch(void* const* d_in, const int* in_sizes, int n_in,
                              void* d_out, int out_size) {
    const float* x    = (const float*)d_in[0];
    const int*   tseq = (const int*)d_in[1];
    const float* emb  = (const float*)d_in[2];
    const float* Wx   = (const float*)d_in[3];
    const float* Wh   = (const float*)d_in[4];
    const float* b1   = (const float*)d_in[5];
    const float* w2   = (const float*)d_in[6];
    const float* b2   = (const float*)d_in[7];
    const float* fcW  = (const float*)d_in[8];
    const float* fcb  = (const float*)d_in[9];
    const float* Wih0 = (const float*)d_in[10];
    const float* Whh0 = (const float*)d_in[11];
    const float* bih0 = (const float*)d_in[12];
    const float* bhh0 = (const float*)d_in[13];
    const float* Wih1 = (const float*)d_in[14];
    const float* Whh1 = (const float*)d_in[15];
    const float* bih1 = (const float*)d_in[16];
    const float* bhh1 = (const float*)d_in[17];
    const float* Wih2 = (const float*)d_in[18];
    const float* Whh2 = (const float*)d_in[19];
    const float* bih2 = (const float*)d_in[20];
    const float* bhh2 = (const float*)d_in[21];
    float* dout = (float*)d_out;

    static cudaStream_t s2 = nullptr;
    static cudaEvent_t evA = nullptr, evB = nullptr, evEnd = nullptr;
    if (!s2) {
        cudaStreamCreateWithFlags(&s2, cudaStreamNonBlocking);
        cudaEventCreateWithFlags(&evA, cudaEventDisableTiming);
        cudaEventCreateWithFlags(&evB, cudaEventDisableTiming);
        cudaEventCreateWithFlags(&evEnd, cudaEventDisableTiming);
    }

    // -------- prologue (single kernel + x_proj) --------
    // flat threads: 7,733,248 (pack) + 1,572,864 (cvt x) + 49,152 (zero) = 9,355,264
    prolog_combined<<<36544, 256>>>(Wx, Wh, Wih0, Whh0, Wih1, Whh1, Wih2, Whh2, fcW, x);
    // x_proj: M=2048, N=1024 (4 nblocks), K=768 (48 chunks), bf16 out
    gemm_v4<false><<<dim3(4, 128, 1), 256>>>(0, EE, 0, 0, nullptr, (long long)HH, 0,
                                             b1, 48);

    // -------- time loop --------
    for (int t = 0; t < TT; t++) {
        // hv = h2 @ Wh : N=1024 (4 nblocks), split-K=8 (8 chunks each)
        gemm_v4<false><<<dim3(4, 1, 8), 256>>>(4, 2048, 1, 1, nullptr, (long long)HH,
                                               BB * HH, nullptr, 8);
        attn_fused<<<BB, 1024>>>(w2, b2, tseq, emb, t);
        // layer 0: N=4096 (16 nblocks), K=2560 split-K=8 (20 chunks each)
        gemm_v4<false><<<dim3(16, 1, 8), 256>>>(1, 2560, 2, 2, nullptr, (long long)4096,
                                                BB * 4096, nullptr, 20);
        lstm_cell<<<64, 256>>>(bih0, bhh0, 0);
        // layer 1: K=2048 split-K=8 (16 chunks each)
        gemm_v4<false><<<dim3(16, 1, 8), 256>>>(2, 2048, 3, 2, nullptr, (long long)4096,
                                                BB * 4096, nullptr, 16);
        lstm_cell<<<64, 256>>>(bih1, bhh1, 1);
        // layer 2
        gemm_v4<false><<<dim3(16, 1, 8), 256>>>(3, 2048, 4, 2, nullptr, (long long)4096,
                                                BB * 4096, nullptr, 16);
        // cell2 overwrites h2 -> must wait for previous step's fc (reads h2)
        if (t > 0) cudaStreamWaitEvent(0, evB, 0);
        lstm_cell<<<64, 256>>>(bih2, bhh2, 2);

        // fork fc + lsm onto side stream (depends only on cell2 of this step)
        cudaEventRecord(evA, 0);
        cudaStreamWaitEvent(s2, evA, 0);
        // fc: N=32000 (125 nblocks), K=1024 (64 chunks), streaming weights
        gemm_v4<true><<<dim3(125, 1, 1), 256, 0, s2>>>(4, 2048, 5, 3,
                                                       dout + (long long)t * VV,
                                                       (long long)TT * VV, 0, fcb, 64);
        cudaEventRecord(evB, s2);
        lsm_kernel<<<BB, 1024, 0, s2>>>(dout, t);
    }
    // join side stream back before capture ends
    cudaEventRecord(evEnd, s2);
    cudaStreamWaitEvent(0, evEnd, 0);
}

// round 12
// speedup vs baseline: 1.2408x; 1.1163x over previous
#include <cuda_runtime.h>
#include <cuda_bf16.h>
#include <cstdint>

#define BB 16
#define SS 128
#define TT 64
#define EE 768
#define HH 1024
#define VV 32000

// ---------------- device scratch (static, no allocation) ----------------
__device__ __nv_bfloat16 g_xbf[BB * SS * EE];        // x bf16
__device__ __nv_bfloat16 g_xprojbf[BB * SS * HH];    // x@Wx + b1, bf16
// fragment-packed weights: uint4 per (ntile16, kchunk16, lane)
__device__ uint4 g_pWx[(HH / 16) * (EE / 16) * 32];
__device__ uint4 g_pWh[(HH / 16) * (HH / 16) * 32];
__device__ uint4 g_pWc0[(4096 / 16) * (2560 / 16) * 32];
__device__ uint4 g_pWc1[(4096 / 16) * (2048 / 16) * 32];
__device__ uint4 g_pWc2[(4096 / 16) * (2048 / 16) * 32];
__device__ uint4 g_pFc[(VV / 16) * (HH / 16) * 32];

__device__ __nv_bfloat16 g_A0[BB * 2560];   // [emb | ctx | h0]
__device__ __nv_bfloat16 g_A1[BB * 2048];   // [h0_new | h1_prev]
__device__ __nv_bfloat16 g_A2[BB * 2048];   // [h1_new | h2]
__device__ float         g_c[3 * BB * HH];  // cell states
__device__ float         g_hvp[8 * BB * HH];     // h2@Wh split-K partials
__device__ float         g_part[8 * BB * 4096]; // LSTM gate split-K partials
__device__ float         g_sc[BB * SS];          // attention scores

// ---------------- single combined prologue (pack + cvt_x + zero) ----------------
__global__ void prolog_combined(
    const float* __restrict__ Wx, const float* __restrict__ Wh,
    const float* __restrict__ Wih0, const float* __restrict__ Whh0,
    const float* __restrict__ Wih1, const float* __restrict__ Whh1,
    const float* __restrict__ Wih2, const float* __restrict__ Whh2,
    const float* __restrict__ fcW, const float* __restrict__ x) {
    const long long C0 = 98304, C1 = C0 + 131072, C2 = C1 + 1310720,
                    C3 = C2 + 1048576, C4 = C3 + 1048576, C5 = C4 + 4096000;
    long long idx = (long long)blockIdx.x * 256 + threadIdx.x;
    if (idx < C5) {
        uint4* dst; const float *s1, *s2 = nullptr;
        int N, K1, K2 = 0, tr; long long base;
        if (idx < C0)      { dst = g_pWx;  s1 = Wx;   N = HH;   K1 = EE;   tr = 1; base = 0; }
        else if (idx < C1) { dst = g_pWh;  s1 = Wh;   N = HH;   K1 = HH;   tr = 1; base = C0; }
        else if (idx < C2) { dst = g_pWc0; s1 = Wih0; s2 = Whh0; N = 4096; K1 = 1536; K2 = 1024; tr = 0; base = C1; }
        else if (idx < C3) { dst = g_pWc1; s1 = Wih1; s2 = Whh1; N = 4096; K1 = 1024; K2 = 1024; tr = 0; base = C2; }
        else if (idx < C4) { dst = g_pWc2; s1 = Wih2; s2 = Whh2; N = 4096; K1 = 1024; K2 = 1024; tr = 0; base = C3; }
        else               { dst = g_pFc;  s1 = fcW;  N = VV;   K1 = HH;   tr = 0; base = C4; }
        long long li = idx - base;
        int nch = (K1 + K2) >> 4;
        int lane = (int)(li & 31);
        long long tt = li >> 5;
        int ch = (int)(tt % nch);
        int nt = (int)(tt / nch);
        int g = lane >> 2, tig = lane & 3;
        int k = ch * 16 + tig * 2;
        int r0 = nt * 16 + g, r1 = r0 + 8;
        auto ld = [&](int n, int kk) -> float {
            if (kk < K1) return tr ? s1[(long long)kk * N + n] : s1[(long long)n * K1 + kk];
            return s2[(long long)n * HH + (kk - K1)];
        };
        auto p2 = [&](float a, float b) -> unsigned {
            __nv_bfloat162 h = __floats2bfloat162_rn(a, b);
            return *reinterpret_cast<unsigned*>(&h);
        };
        uint4 v;
        v.x = p2(ld(r0, k), ld(r0, k + 1));
        v.y = p2(ld(r0, k + 8), ld(r0, k + 9));
        v.z = p2(ld(r1, k), ld(r1, k + 1));
        v.w = p2(ld(r1, k + 8), ld(r1, k + 9));
        dst[li] = v;
        return;
    }
    long long r = idx - C5;
    if (r < (long long)BB * SS * EE) {  // x -> bf16
        g_xbf[r] = __float2bfloat16(x[r]);
        return;
    }
    r -= (long long)BB * SS * EE;
    if (r < 3 * BB * HH) {  // zero state + h slots
        g_c[r] = 0.f;
        __nv_bfloat16 z = __float2bfloat16(0.f);
        if (r < BB * HH) {
            int b = (int)(r >> 10), j = (int)(r & 1023);
            g_A0[b * 2560 + 1536 + j] = z;
        }
        if (r < BB * 2048) { g_A1[r] = z; g_A2[r] = z; }
    }
}

// ---------------- 16xN bf16 tensor-core GEMM ----------------
__device__ __forceinline__ const __nv_bfloat16* selA(int t) {
    switch (t) {
        case 0: return g_xbf;
        case 1: return g_A0;
        case 2: return g_A1;
        case 3: return g_A2;
        default: return g_A2 + 1024;  // h2 slice
    }
}

__device__ __forceinline__ void mma16816(float c[4], uint32_t a0, uint32_t a1, uint32_t a2,
                                         uint32_t a3, uint32_t b0, uint32_t b1) {
    asm volatile(
        "mma.sync.aligned.m16n8k16.row.col.f32.bf16.bf16.f32 "
        "{%0,%1,%2,%3}, {%4,%5,%6,%7}, {%8,%9}, {%0,%1,%2,%3};\n"
        : "+f"(c[0]), "+f"(c[1]), "+f"(c[2]), "+f"(c[3])
        : "r"(a0), "r"(a1), "r"(a2), "r"(a3), "r"(b0), "r"(b1));
}

#define APAD 8
#define AMAXC (64 * 16)

// cTag: 0 = g_xprojbf (bf16), 1 = g_hvp, 2 = g_part, 3 = external fp32 (dout)
template <bool EF>
__global__ __launch_bounds__(256) void gemm_v4(
    int aTag, int lda, int bTag, int cTag, float* cExt, long long ldc,
    int partStride, const float* __restrict__ bias, int nCh) {
    __shared__ __nv_bfloat16 s_a[16][AMAXC + APAD];
    const __nv_bfloat16* A = selA(aTag);
    const uint4* B;
    int nchTot;
    switch (bTag) {
        case 0: B = g_pWx;  nchTot = EE / 16;   break;
        case 1: B = g_pWh;  nchTot = HH / 16;   break;
        case 2: B = g_pWc0; nchTot = 2560 / 16; break;
        case 3: B = g_pWc1; nchTot = 2048 / 16; break;
        case 4: B = g_pWc2; nchTot = 2048 / 16; break;
        default: B = g_pFc; nchTot = HH / 16;   break;
    }
    int w = threadIdx.x >> 5, lane = threadIdx.x & 31;
    int g = lane >> 2, tig = lane & 3;
    int m0 = blockIdx.y * 16;
    int n0 = blockIdx.x * 256 + w * 32;
    int ch0 = blockIdx.z * nCh;

    {   // stage A slice (16 x nCh*16) into padded smem, coalesced uint4
        int cols4 = nCh * 2;
        for (int idx = threadIdx.x; idx < 16 * cols4; idx += 256) {
            int r = idx / cols4, cc = idx % cols4;
            uint4 v = *reinterpret_cast<const uint4*>(
                A + (long long)(m0 + r) * lda + ch0 * 16 + cc * 8);
            *reinterpret_cast<uint4*>(&s_a[r][cc * 8]) = v;
        }
    }
    __syncthreads();

    const uint4* bp0 = B + ((long long)(n0 >> 4) * nchTot + ch0) * 32 + lane;
    const uint4* bp1 = bp0 + (long long)nchTot * 32;
    uint32_t sab = (uint32_t)__cvta_generic_to_shared(&s_a[lane & 15][(lane >> 4) * 8]);

    float acc[4][4] = {{0.f}, {0.f}, {0.f}, {0.f}};
#pragma unroll 8
    for (int c = 0; c < nCh; c++) {
        uint4 b0 = EF ? __ldcs(bp0 + (long long)c * 32) : __ldg(bp0 + (long long)c * 32);
        uint4 b1 = EF ? __ldcs(bp1 + (long long)c * 32) : __ldg(bp1 + (long long)c * 32);
        uint32_t a0, a1, a2, a3;
        asm volatile("ldmatrix.sync.aligned.m8n8.x4.shared.b16 {%0,%1,%2,%3}, [%4];"
                     : "=r"(a0), "=r"(a1), "=r"(a2), "=r"(a3)
                     : "r"(sab + (uint32_t)c * 32));
        mma16816(acc[0], a0, a1, a2, a3, b0.x, b0.y);
        mma16816(acc[1], a0, a1, a2, a3, b0.z, b0.w);
        mma16816(acc[2], a0, a1, a2, a3, b1.x, b1.y);
        mma16816(acc[3], a0, a1, a2, a3, b1.z, b1.w);
    }

    int r0 = m0 + g, r1 = m0 + g + 8;
    if (cTag == 0) {
        __nv_bfloat16* Cb = g_xprojbf;
#pragma unroll
        for (int q = 0; q < 4; q++) {
            int col = n0 + q * 8 + tig * 2;
            float bv0 = bias[col], bv1 = bias[col + 1];
            Cb[(long long)r0 * ldc + col]     = __float2bfloat16(acc[q][0] + bv0);
            Cb[(long long)r0 * ldc + col + 1] = __float2bfloat16(acc[q][1] + bv1);
            Cb[(long long)r1 * ldc + col]     = __float2bfloat16(acc[q][2] + bv0);
            Cb[(long long)r1 * ldc + col + 1] = __float2bfloat16(acc[q][3] + bv1);
        }
        return;
    }
    float* C = (cTag == 1) ? g_hvp : (cTag == 2) ? g_part : cExt;
    C += (long long)blockIdx.z * partStride;
#pragma unroll
    for (int q = 0; q < 4; q++) {
        int col = n0 + q * 8 + tig * 2;
        float bv0 = bias ? bias[col] : 0.f, bv1 = bias ? bias[col + 1] : 0.f;
        C[(long long)r0 * ldc + col]     = acc[q][0] + bv0;
        C[(long long)r0 * ldc + col + 1] = acc[q][1] + bv1;
        C[(long long)r1 * ldc + col]     = acc[q][2] + bv0;
        C[(long long)r1 * ldc + col + 1] = acc[q][3] + bv1;
    }
}

// ---------------- attention stage 1: scores (wide: 8 s-chunks x 16 b) ----------------
__global__ __launch_bounds__(256) void attn_score(
    const float* __restrict__ w2, const float* __restrict__ b2) {
    __shared__ float hv_s[HH];
    __shared__ float w2_s[HH];
    int b = blockIdx.y, sch = blockIdx.x, tid = threadIdx.x;
    for (int i = tid; i < HH; i += 256) {
        float s = 0.f;
#pragma unroll
        for (int p = 0; p < 8; p++) s += g_hvp[p * BB * HH + b * HH + i];
        hv_s[i] = s;
        w2_s[i] = w2[i];
    }
    __syncthreads();
    int w = tid >> 5, lane = tid & 31;
#pragma unroll
    for (int rr = 0; rr < 2; rr++) {
        int s = sch * 16 + w * 2 + rr;
        const __nv_bfloat16* row = g_xprojbf + ((long long)b * SS + s) * HH;
        float sum = 0.f;
#pragma unroll
        for (int it = 0; it < 4; it++) {
            int k0 = it * 256 + lane * 8;
            uint4 v = *reinterpret_cast<const uint4*>(row + k0);
            const __nv_bfloat162* hp = reinterpret_cast<const __nv_bfloat162*>(&v);
#pragma unroll
            for (int j = 0; j < 4; j++) {
                float2 f = __bfloat1622float2(hp[j]);
                int k = k0 + j * 2;
                float a = f.x + hv_s[k];
                float c = f.y + hv_s[k + 1];
                sum += (a > 0.f ? a * w2_s[k] : 0.f) + (c > 0.f ? c * w2_s[k + 1] : 0.f);
            }
        }
#pragma unroll
        for (int o = 16; o; o >>= 1) sum += __shfl_xor_sync(0xffffffffu, sum, o);
        if (!lane) g_sc[b * SS + s] = sum + b2[0];
    }
}

// ---------------- attention stage 2: log-softmax + context + emb (4 e-chunks x 16 b) ----------------
__global__ __launch_bounds__(256) void attn_ctx2(
    const int* __restrict__ tseq, const float* __restrict__ emb, int t) {
    __shared__ float sc[SS];
    __shared__ float red;
    int b = blockIdx.y, ech = blockIdx.x, tid = threadIdx.x;
    if (tid < SS) sc[tid] = g_sc[b * SS + tid];
    __syncthreads();
    if (tid < 32) {
        float m = -1e30f;
#pragma unroll
        for (int i = 0; i < 4; i++) m = fmaxf(m, sc[tid + i * 32]);
#pragma unroll
        for (int o = 16; o; o >>= 1) m = fmaxf(m, __shfl_xor_sync(0xffffffffu, m, o));
        float su = 0.f;
#pragma unroll
        for (int i = 0; i < 4; i++) su += expf(sc[tid + i * 32] - m);
#pragma unroll
        for (int o = 16; o; o >>= 1) su += __shfl_xor_sync(0xffffffffu, su, o);
        if (!tid) red = m + logf(su);
    }
    __syncthreads();
    float lse = red;
    __syncthreads();
    if (tid < SS) sc[tid] -= lse;
    __syncthreads();
    if (tid < 192) {
        int e = ech * 192 + tid;
        const __nv_bfloat16* xb = g_xbf + (long long)b * SS * EE + e;
        float acc = 0.f;
#pragma unroll 8
        for (int s = 0; s < SS; s++) acc += sc[s] * __bfloat162float(xb[(long long)s * EE]);
        g_A0[b * 2560 + EE + e] = __float2bfloat16(acc);
        int tok = tseq[b * TT + t];
        g_A0[b * 2560 + e] = __float2bfloat16(emb[(long long)tok * EE + e]);
    }
}

// ---------------- LSTM cell elementwise (sums 8 split-K partials) ----------------
__global__ __launch_bounds__(256) void lstm_cell(
    const float* __restrict__ bih, const float* __restrict__ bhh, int layer) {
    int idx = blockIdx.x * 256 + threadIdx.x;  // 16384
    int b = idx >> 10, j = idx & 1023;
    float gi = bih[j] + bhh[j];
    float gf = bih[1024 + j] + bhh[1024 + j];
    float gg = bih[2048 + j] + bhh[2048 + j];
    float go = bih[3072 + j] + bhh[3072 + j];
#pragma unroll
    for (int p = 0; p < 8; p++) {
        const float* pp = g_part + p * (BB * 4096) + b * 4096;
        gi += pp[j];
        gf += pp[1024 + j];
        gg += pp[2048 + j];
        go += pp[3072 + j];
    }
    float si = 1.f / (1.f + expf(-gi));
    float sf = 1.f / (1.f + expf(-gf));
    float so = 1.f / (1.f + expf(-go));
    float* cc = g_c + layer * (BB * HH) + idx;
    float cn = sf * (*cc) + si * tanhf(gg);
    *cc = cn;
    float h = so * tanhf(cn);
    __nv_bfloat16 hb = __float2bfloat16(h);
    if (layer == 0) {
        g_A1[b * 2048 + j] = hb;
        g_A0[b * 2560 + 1536 + j] = hb;
    } else if (layer == 1) {
        g_A2[b * 2048 + j] = hb;
        g_A1[b * 2048 + 1024 + j] = hb;
    } else {
        g_A2[b * 2048 + 1024 + j] = hb;
    }
}

// ---------------- in-place log_softmax over V (float4) ----------------
__global__ __launch_bounds__(1024) void lsm_kernel(float* __restrict__ dout, int t) {
    float4* row = reinterpret_cast<float4*>(dout + (long long)blockIdx.x * TT * VV +
                                            (long long)t * VV);
    const int NV4 = VV / 4;
    __shared__ float sm[32];
    __shared__ float bc;
    int tid = threadIdx.x, lane = tid & 31, wid = tid >> 5;
    float m = -1e30f;
    for (int i = tid; i < NV4; i += 1024) {
        float4 v = row[i];
        m = fmaxf(m, fmaxf(fmaxf(v.x, v.y), fmaxf(v.z, v.w)));
    }
#pragma unroll
    for (int o = 16; o; o >>= 1) m = fmaxf(m, __shfl_xor_sync(0xffffffffu, m, o));
    if (!lane) sm[wid] = m;
    __syncthreads();
    if (tid < 32) {
        float mm = sm[tid];
#pragma unroll
        for (int o = 16; o; o >>= 1) mm = fmaxf(mm, __shfl_xor_sync(0xffffffffu, mm, o));
        if (!tid) bc = mm;
    }
    __syncthreads();
    m = bc;
    float s = 0.f;
    for (int i = tid; i < NV4; i += 1024) {
        float4 v = row[i];
        s += expf(v.x - m) + expf(v.y - m) + expf(v.z - m) + expf(v.w - m);
    }
#pragma unroll
    for (int o = 16; o; o >>= 1) s += __shfl_xor_sync(0xffffffffu, s, o);
    __syncthreads();
    if (!lane) sm[wid] = s;
    __syncthreads();
    if (tid < 32) {
        float ss = sm[tid];
#pragma unroll
        for (int o = 16; o; o >>= 1) ss += __shfl_xor_sync(0xffffffffu, ss, o);
        if (!tid) bc = m + logf(ss);
    }
    __syncthreads();
    float lse = bc;
    for (int i = tid; i < NV4; i += 1024) {
        float4 v = row[i];
        v.x -= lse; v.y -= lse; v.z -= lse; v.w -= lse;
        row[i] = v;
    }
}

// ---------------- host launch ----------------
extern "C" void kernel_launch(void* const* d_in, const int* in_sizes, int n_in,
                              void* d_out, int out_size) {
    const float* x    = (const float*)d_in[0];
    const int*   tseq = (const int*)d_in[1];
    const float* emb  = (const float*)d_in[2];
    const float* Wx   = (const float*)d_in[3];
    const float* Wh   = (const float*)d_in[4];
    const float* b1   = (const float*)d_in[5];
    const float* w2   = (const float*)d_in[6];
    const float* b2   = (const float*)d_in[7];
    const float* fcW  = (const float*)d_in[8];
    const float* fcb  = (const float*)d_in[9];
    const float* Wih0 = (const float*)d_in[10];
    const float* Whh0 = (const float*)d_in[11];
    const float* bih0 = (const float*)d_in[12];
    const float* bhh0 = (const float*)d_in[13];
    const float* Wih1 = (const float*)d_in[14];
    const float* Whh1 = (const float*)d_in[15];
    const float* bih1 = (const float*)d_in[16];
    const float* bhh1 = (const float*)d_in[17];
    const float* Wih2 = (const float*)d_in[18];
    const float* Whh2 = (const float*)d_in[19];
    const float* bih2 = (const float*)d_in[20];
    const float* bhh2 = (const float*)d_in[21];
    float* dout = (float*)d_out;

    static cudaStream_t s2 = nullptr;
    static cudaEvent_t evA = nullptr, evB = nullptr, evEnd = nullptr;
    if (!s2) {
        cudaStreamCreateWithFlags(&s2, cudaStreamNonBlocking);
        cudaEventCreateWithFlags(&evA, cudaEventDisableTiming);
        cudaEventCreateWithFlags(&evB, cudaEventDisableTiming);
        cudaEventCreateWithFlags(&evEnd, cudaEventDisableTiming);
    }

    // -------- prologue --------
    prolog_combined<<<36544, 256>>>(Wx, Wh, Wih0, Whh0, Wih1, Whh1, Wih2, Whh2, fcW, x);
    // x_proj: M=2048, N=1024 (4 nblocks), K=768 (48 chunks), bf16 out
    gemm_v4<false><<<dim3(4, 128, 1), 256>>>(0, EE, 0, 0, nullptr, (long long)HH, 0,
                                             b1, 48);

    // -------- time loop --------
    for (int t = 0; t < TT; t++) {
        // hv = h2 @ Wh : split-K=8
        gemm_v4<false><<<dim3(4, 1, 8), 256>>>(4, 2048, 1, 1, nullptr, (long long)HH,
                                               BB * HH, nullptr, 8);
        attn_score<<<dim3(8, BB), 256>>>(w2, b2);
        attn_ctx2<<<dim3(4, BB), 256>>>(tseq, emb, t);
        // layer 0: K=2560 split-K=8 (20 chunks each)
        gemm_v4<false><<<dim3(16, 1, 8), 256>>>(1, 2560, 2, 2, nullptr, (long long)4096,
                                                BB * 4096, nullptr, 20);
        lstm_cell<<<64, 256>>>(bih0, bhh0, 0);
        // layer 1: K=2048 split-K=8 (16 chunks each)
        gemm_v4<false><<<dim3(16, 1, 8), 256>>>(2, 2048, 3, 2, nullptr, (long long)4096,
                                                BB * 4096, nullptr, 16);
        lstm_cell<<<64, 256>>>(bih1, bhh1, 1);
        // layer 2
        gemm_v4<false><<<dim3(16, 1, 8), 256>>>(3, 2048, 4, 2, nullptr, (long long)4096,
                                                BB * 4096, nullptr, 16);
        // cell2 overwrites h2 -> must wait for previous step's fc (reads h2)
        if (t > 0) cudaStreamWaitEvent(0, evB, 0);
        lstm_cell<<<64, 256>>>(bih2, bhh2, 2);

        // fork fc + lsm onto side stream (depends only on cell2 of this step)
        cudaEventRecord(evA, 0);
        cudaStreamWaitEvent(s2, evA, 0);
        gemm_v4<true><<<dim3(125, 1, 1), 256, 0, s2>>>(4, 2048, 5, 3,
                                                       dout + (long long)t * VV,
                                                       (long long)TT * VV, 0, fcb, 64);
        cudaEventRecord(evB, s2);
        lsm_kernel<<<BB, 1024, 0, s2>>>(dout, t);
    }
    // join side stream back before capture ends
    cudaEventRecord(evEnd, s2);
    cudaStreamWaitEvent(0, evEnd, 0);
}

// round 13
// speedup vs baseline: 1.3686x; 1.1030x over previous
#include <cuda_runtime.h>
#include <cuda_bf16.h>
#include <cstdint>

#define BB 16
#define SS 128
#define TT 64
#define EE 768
#define HH 1024
#define VV 32000

// ---------------- device scratch (static, no allocation) ----------------
__device__ __nv_bfloat16 g_xbf[BB * SS * EE];        // x bf16
__device__ __nv_bfloat16 g_xprojbf[BB * SS * HH];    // x@Wx + b1, bf16
__device__ uint4 g_pWx[(HH / 16) * (EE / 16) * 32];
__device__ uint4 g_pWh[(HH / 16) * (HH / 16) * 32];
__device__ uint4 g_pWc0[(4096 / 16) * (2560 / 16) * 32];
__device__ uint4 g_pWc1[(4096 / 16) * (2048 / 16) * 32];
__device__ uint4 g_pWc2[(4096 / 16) * (2048 / 16) * 32];
__device__ uint4 g_pFc[(VV / 16) * (HH / 16) * 32];

__device__ __nv_bfloat16 g_A0[BB * 2560];   // [emb | ctx | h0]
__device__ __nv_bfloat16 g_A1[BB * 2048];   // [h0_new | h1_prev]
__device__ __nv_bfloat16 g_A2[BB * 2048];   // [h1_new | h2]
__device__ float         g_c[3 * BB * HH];  // cell states
__device__ float         g_hvp[8 * BB * HH];     // h2@Wh split-K partials
__device__ __nv_bfloat16 g_hv[BB * HH];          // reduced hv (bf16)
__device__ __nv_bfloat16 g_w2bf[HH];             // w2 bf16
__device__ float         g_part[8 * BB * 4096]; // LSTM gate split-K partials
__device__ float         g_sc[BB * SS];          // attention scores

// ---------------- single combined prologue (pack + cvt_x + zero + emb0 + w2) ----
__global__ void prolog_combined(
    const float* __restrict__ Wx, const float* __restrict__ Wh,
    const float* __restrict__ Wih0, const float* __restrict__ Whh0,
    const float* __restrict__ Wih1, const float* __restrict__ Whh1,
    const float* __restrict__ Wih2, const float* __restrict__ Whh2,
    const float* __restrict__ fcW, const float* __restrict__ x,
    const int* __restrict__ tseq, const float* __restrict__ emb,
    const float* __restrict__ w2) {
    const long long C0 = 98304, C1 = C0 + 131072, C2 = C1 + 1310720,
                    C3 = C2 + 1048576, C4 = C3 + 1048576, C5 = C4 + 4096000;
    long long idx = (long long)blockIdx.x * 256 + threadIdx.x;
    if (idx < C5) {
        uint4* dst; const float *s1, *s2 = nullptr;
        int N, K1, K2 = 0, tr; long long base;
        if (idx < C0)      { dst = g_pWx;  s1 = Wx;   N = HH;   K1 = EE;   tr = 1; base = 0; }
        else if (idx < C1) { dst = g_pWh;  s1 = Wh;   N = HH;   K1 = HH;   tr = 1; base = C0; }
        else if (idx < C2) { dst = g_pWc0; s1 = Wih0; s2 = Whh0; N = 4096; K1 = 1536; K2 = 1024; tr = 0; base = C1; }
        else if (idx < C3) { dst = g_pWc1; s1 = Wih1; s2 = Whh1; N = 4096; K1 = 1024; K2 = 1024; tr = 0; base = C2; }
        else if (idx < C4) { dst = g_pWc2; s1 = Wih2; s2 = Whh2; N = 4096; K1 = 1024; K2 = 1024; tr = 0; base = C3; }
        else               { dst = g_pFc;  s1 = fcW;  N = VV;   K1 = HH;   tr = 0; base = C4; }
        long long li = idx - base;
        int nch = (K1 + K2) >> 4;
        int lane = (int)(li & 31);
        long long tt = li >> 5;
        int ch = (int)(tt % nch);
        int nt = (int)(tt / nch);
        int g = lane >> 2, tig = lane & 3;
        int k = ch * 16 + tig * 2;
        int r0 = nt * 16 + g, r1 = r0 + 8;
        auto ld = [&](int n, int kk) -> float {
            if (kk < K1) return tr ? s1[(long long)kk * N + n] : s1[(long long)n * K1 + kk];
            return s2[(long long)n * HH + (kk - K1)];
        };
        auto p2 = [&](float a, float b) -> unsigned {
            __nv_bfloat162 h = __floats2bfloat162_rn(a, b);
            return *reinterpret_cast<unsigned*>(&h);
        };
        uint4 v;
        v.x = p2(ld(r0, k), ld(r0, k + 1));
        v.y = p2(ld(r0, k + 8), ld(r0, k + 9));
        v.z = p2(ld(r1, k), ld(r1, k + 1));
        v.w = p2(ld(r1, k + 8), ld(r1, k + 9));
        dst[li] = v;
        return;
    }
    long long r = idx - C5;
    if (r < (long long)BB * SS * EE) {  // x -> bf16
        g_xbf[r] = __float2bfloat16(x[r]);
        return;
    }
    r -= (long long)BB * SS * EE;
    if (r < 3 * BB * HH) {  // zero state + h slots
        g_c[r] = 0.f;
        __nv_bfloat16 z = __float2bfloat16(0.f);
        if (r < BB * HH) {
            int b = (int)(r >> 10), j = (int)(r & 1023);
            g_A0[b * 2560 + 1536 + j] = z;
        }
        if (r < BB * 2048) { g_A1[r] = z; g_A2[r] = z; }
        return;
    }
    r -= 3 * BB * HH;
    if (r < BB * EE) {  // emb gather for t=0
        int b = (int)(r / EE), e = (int)(r % EE);
        int tok = tseq[b * TT];
        g_A0[b * 2560 + e] = __float2bfloat16(emb[(long long)tok * EE + e]);
        return;
    }
    r -= BB * EE;
    if (r < HH) g_w2bf[r] = __float2bfloat16(w2[r]);
}

// ---------------- 16xN bf16 tensor-core GEMM ----------------
__device__ __forceinline__ const __nv_bfloat16* selA(int t) {
    switch (t) {
        case 0: return g_xbf;
        case 1: return g_A0;
        case 2: return g_A1;
        case 3: return g_A2;
        default: return g_A2 + 1024;  // h2 slice
    }
}

__device__ __forceinline__ void mma16816(float c[4], uint32_t a0, uint32_t a1, uint32_t a2,
                                         uint32_t a3, uint32_t b0, uint32_t b1) {
    asm volatile(
        "mma.sync.aligned.m16n8k16.row.col.f32.bf16.bf16.f32 "
        "{%0,%1,%2,%3}, {%4,%5,%6,%7}, {%8,%9}, {%0,%1,%2,%3};\n"
        : "+f"(c[0]), "+f"(c[1]), "+f"(c[2]), "+f"(c[3])
        : "r"(a0), "r"(a1), "r"(a2), "r"(a3), "r"(b0), "r"(b1));
}

#define APAD 8
#define AMAXC (64 * 16)

// cTag: 0 = g_xprojbf (bf16), 1 = g_hvp, 2 = g_part, 3 = external fp32 (dout)
template <bool EF>
__global__ __launch_bounds__(256) void gemm_v4(
    int aTag, int lda, int bTag, int cTag, float* cExt, long long ldc,
    int partStride, const float* __restrict__ bias, int nCh) {
    __shared__ __nv_bfloat16 s_a[16][AMAXC + APAD];
    const __nv_bfloat16* A = selA(aTag);
    const uint4* B;
    int nchTot;
    switch (bTag) {
        case 0: B = g_pWx;  nchTot = EE / 16;   break;
        case 1: B = g_pWh;  nchTot = HH / 16;   break;
        case 2: B = g_pWc0; nchTot = 2560 / 16; break;
        case 3: B = g_pWc1; nchTot = 2048 / 16; break;
        case 4: B = g_pWc2; nchTot = 2048 / 16; break;
        default: B = g_pFc; nchTot = HH / 16;   break;
    }
    int w = threadIdx.x >> 5, lane = threadIdx.x & 31;
    int g = lane >> 2, tig = lane & 3;
    int m0 = blockIdx.y * 16;
    int n0 = blockIdx.x * 256 + w * 32;
    int ch0 = blockIdx.z * nCh;

    {   // stage A slice (16 x nCh*16) into padded smem, coalesced uint4
        int cols4 = nCh * 2;
        for (int idx = threadIdx.x; idx < 16 * cols4; idx += 256) {
            int r = idx / cols4, cc = idx % cols4;
            uint4 v = *reinterpret_cast<const uint4*>(
                A + (long long)(m0 + r) * lda + ch0 * 16 + cc * 8);
            *reinterpret_cast<uint4*>(&s_a[r][cc * 8]) = v;
        }
    }
    __syncthreads();

    const uint4* bp0 = B + ((long long)(n0 >> 4) * nchTot + ch0) * 32 + lane;
    const uint4* bp1 = bp0 + (long long)nchTot * 32;
    uint32_t sab = (uint32_t)__cvta_generic_to_shared(&s_a[lane & 15][(lane >> 4) * 8]);

    float acc[4][4] = {{0.f}, {0.f}, {0.f}, {0.f}};
#pragma unroll 8
    for (int c = 0; c < nCh; c++) {
        uint4 b0 = EF ? __ldcs(bp0 + (long long)c * 32) : __ldg(bp0 + (long long)c * 32);
        uint4 b1 = EF ? __ldcs(bp1 + (long long)c * 32) : __ldg(bp1 + (long long)c * 32);
        uint32_t a0, a1, a2, a3;
        asm volatile("ldmatrix.sync.aligned.m8n8.x4.shared.b16 {%0,%1,%2,%3}, [%4];"
                     : "=r"(a0), "=r"(a1), "=r"(a2), "=r"(a3)
                     : "r"(sab + (uint32_t)c * 32));
        mma16816(acc[0], a0, a1, a2, a3, b0.x, b0.y);
        mma16816(acc[1], a0, a1, a2, a3, b0.z, b0.w);
        mma16816(acc[2], a0, a1, a2, a3, b1.x, b1.y);
        mma16816(acc[3], a0, a1, a2, a3, b1.z, b1.w);
    }

    int r0 = m0 + g, r1 = m0 + g + 8;
    if (cTag == 0) {
        __nv_bfloat16* Cb = g_xprojbf;
#pragma unroll
        for (int q = 0; q < 4; q++) {
            int col = n0 + q * 8 + tig * 2;
            float bv0 = bias[col], bv1 = bias[col + 1];
            Cb[(long long)r0 * ldc + col]     = __float2bfloat16(acc[q][0] + bv0);
            Cb[(long long)r0 * ldc + col + 1] = __float2bfloat16(acc[q][1] + bv1);
            Cb[(long long)r1 * ldc + col]     = __float2bfloat16(acc[q][2] + bv0);
            Cb[(long long)r1 * ldc + col + 1] = __float2bfloat16(acc[q][3] + bv1);
        }
        return;
    }
    float* C = (cTag == 1) ? g_hvp : (cTag == 2) ? g_part : cExt;
    C += (long long)blockIdx.z * partStride;
#pragma unroll
    for (int q = 0; q < 4; q++) {
        int col = n0 + q * 8 + tig * 2;
        float bv0 = bias ? bias[col] : 0.f, bv1 = bias ? bias[col + 1] : 0.f;
        C[(long long)r0 * ldc + col]     = acc[q][0] + bv0;
        C[(long long)r0 * ldc + col + 1] = acc[q][1] + bv1;
        C[(long long)r1 * ldc + col]     = acc[q][2] + bv0;
        C[(long long)r1 * ldc + col + 1] = acc[q][3] + bv1;
    }
}

// ---------------- hv reduce: 8 partials -> bf16 ----------------
__global__ __launch_bounds__(256) void hv_reduce() {
    int i = blockIdx.x * 256 + threadIdx.x;  // 16384
    float s = 0.f;
#pragma unroll
    for (int p = 0; p < 8; p++) s += g_hvp[p * BB * HH + i];
    g_hv[i] = __float2bfloat16(s);
}

// ---------------- attention stage 1: scores (256 blocks, 1 score/warp) ----------------
__global__ __launch_bounds__(256) void attn_score(const float* __restrict__ b2) {
    int b = blockIdx.y, sch = blockIdx.x;
    int w = threadIdx.x >> 5, lane = threadIdx.x & 31;
    int s = sch * 8 + w;
    const __nv_bfloat16* row = g_xprojbf + ((long long)b * SS + s) * HH;
    const __nv_bfloat16* hv = g_hv + b * HH;
    float sum = 0.f;
#pragma unroll
    for (int it = 0; it < 4; it++) {
        int k0 = it * 256 + lane * 8;
        uint4 xv = *reinterpret_cast<const uint4*>(row + k0);
        uint4 hvv = *reinterpret_cast<const uint4*>(hv + k0);
        uint4 wv = *reinterpret_cast<const uint4*>(g_w2bf + k0);
        const __nv_bfloat162* xp = reinterpret_cast<const __nv_bfloat162*>(&xv);
        const __nv_bfloat162* hp = reinterpret_cast<const __nv_bfloat162*>(&hvv);
        const __nv_bfloat162* wp = reinterpret_cast<const __nv_bfloat162*>(&wv);
#pragma unroll
        for (int j = 0; j < 4; j++) {
            float2 xf = __bfloat1622float2(xp[j]);
            float2 hf = __bfloat1622float2(hp[j]);
            float2 wf = __bfloat1622float2(wp[j]);
            float a = xf.x + hf.x;
            float c = xf.y + hf.y;
            sum += (a > 0.f ? a * wf.x : 0.f) + (c > 0.f ? c * wf.y : 0.f);
        }
    }
#pragma unroll
    for (int o = 16; o; o >>= 1) sum += __shfl_xor_sync(0xffffffffu, sum, o);
    if (!lane) g_sc[b * SS + s] = sum + b2[0];
}

// ---------------- attention stage 2: log-softmax + context (192 blocks) ----------------
__global__ __launch_bounds__(256) void attn_ctx2() {
    __shared__ float sc[SS];
    __shared__ float red;
    __shared__ float s_part[4][64];
    int b = blockIdx.y, ech = blockIdx.x, tid = threadIdx.x;
    if (tid < SS) sc[tid] = g_sc[b * SS + tid];
    __syncthreads();
    if (tid < 32) {
        float m = -1e30f;
#pragma unroll
        for (int i = 0; i < 4; i++) m = fmaxf(m, sc[tid + i * 32]);
#pragma unroll
        for (int o = 16; o; o >>= 1) m = fmaxf(m, __shfl_xor_sync(0xffffffffu, m, o));
        float su = 0.f;
#pragma unroll
        for (int i = 0; i < 4; i++) su += expf(sc[tid + i * 32] - m);
#pragma unroll
        for (int o = 16; o; o >>= 1) su += __shfl_xor_sync(0xffffffffu, su, o);
        if (!tid) red = m + logf(su);
    }
    __syncthreads();
    float lse = red;
    if (tid < SS) sc[tid] -= lse;
    __syncthreads();
    int q = tid >> 6, e = tid & 63;
    int eg = ech * 64 + e;
    const __nv_bfloat16* xb = g_xbf + ((long long)b * SS + q * 32) * EE + eg;
    float acc = 0.f;
#pragma unroll 8
    for (int ss = 0; ss < 32; ss++)
        acc += sc[q * 32 + ss] * __bfloat162float(xb[(long long)ss * EE]);
    s_part[q][e] = acc;
    __syncthreads();
    if (tid < 64) {
        float a = s_part[0][tid] + s_part[1][tid] + s_part[2][tid] + s_part[3][tid];
        g_A0[b * 2560 + EE + ech * 64 + tid] = __float2bfloat16(a);
    }
}

// ---------------- LSTM cell (sums 8 partials; layer2 also gathers emb t+1) ---------
__global__ __launch_bounds__(256) void lstm_cell(
    const float* __restrict__ bih, const float* __restrict__ bhh, int layer,
    const int* __restrict__ tseq, const float* __restrict__ emb, int t) {
    int idx = blockIdx.x * 256 + threadIdx.x;  // 16384
    int b = idx >> 10, j = idx & 1023;
    float gi = bih[j] + bhh[j];
    float gf = bih[1024 + j] + bhh[1024 + j];
    float gg = bih[2048 + j] + bhh[2048 + j];
    float go = bih[3072 + j] + bhh[3072 + j];
#pragma unroll
    for (int p = 0; p < 8; p++) {
        const float* pp = g_part + p * (BB * 4096) + b * 4096;
        gi += pp[j];
        gf += pp[1024 + j];
        gg += pp[2048 + j];
        go += pp[3072 + j];
    }
    float si = 1.f / (1.f + expf(-gi));
    float sf = 1.f / (1.f + expf(-gf));
    float so = 1.f / (1.f + expf(-go));
    float* cc = g_c + layer * (BB * HH) + idx;
    float cn = sf * (*cc) + si * tanhf(gg);
    *cc = cn;
    float h = so * tanhf(cn);
    __nv_bfloat16 hb = __float2bfloat16(h);
    if (layer == 0) {
        g_A1[b * 2048 + j] = hb;
        g_A0[b * 2560 + 1536 + j] = hb;
    } else if (layer == 1) {
        g_A2[b * 2048 + j] = hb;
        g_A1[b * 2048 + 1024 + j] = hb;
    } else {
        g_A2[b * 2048 + 1024 + j] = hb;
        // gather emb for step t+1 (off the attention critical path)
        if (t + 1 < TT && idx < BB * EE) {
            int be = idx / EE, e = idx % EE;
            int tok = tseq[be * TT + t + 1];
            g_A0[be * 2560 + e] = __float2bfloat16(emb[(long long)tok * EE + e]);
        }
    }
}

// ---------------- in-place log_softmax over V (float4) ----------------
__global__ __launch_bounds__(1024) void lsm_kernel(float* __restrict__ dout, int t) {
    float4* row = reinterpret_cast<float4*>(dout + (long long)blockIdx.x * TT * VV +
                                            (long long)t * VV);
    const int NV4 = VV / 4;
    __shared__ float sm[32];
    __shared__ float bc;
    int tid = threadIdx.x, lane = tid & 31, wid = tid >> 5;
    float m = -1e30f;
    for (int i = tid; i < NV4; i += 1024) {
        float4 v = row[i];
        m = fmaxf(m, fmaxf(fmaxf(v.x, v.y), fmaxf(v.z, v.w)));
    }
#pragma unroll
    for (int o = 16; o; o >>= 1) m = fmaxf(m, __shfl_xor_sync(0xffffffffu, m, o));
    if (!lane) sm[wid] = m;
    __syncthreads();
    if (tid < 32) {
        float mm = sm[tid];
#pragma unroll
        for (int o = 16; o; o >>= 1) mm = fmaxf(mm, __shfl_xor_sync(0xffffffffu, mm, o));
        if (!tid) bc = mm;
    }
    __syncthreads();
    m = bc;
    float s = 0.f;
    for (int i = tid; i < NV4; i += 1024) {
        float4 v = row[i];
        s += expf(v.x - m) + expf(v.y - m) + expf(v.z - m) + expf(v.w - m);
    }
#pragma unroll
    for (int o = 16; o; o >>= 1) s += __shfl_xor_sync(0xffffffffu, s, o);
    __syncthreads();
    if (!lane) sm[wid] = s;
    __syncthreads();
    if (tid < 32) {
        float ss = sm[tid];
#pragma unroll
        for (int o = 16; o; o >>= 1) ss += __shfl_xor_sync(0xffffffffu, ss, o);
        if (!tid) bc = m + logf(ss);
    }
    __syncthreads();
    float lse = bc;
    for (int i = tid; i < NV4; i += 1024) {
        float4 v = row[i];
        v.x -= lse; v.y -= lse; v.z -= lse; v.w -= lse;
        row[i] = v;
    }
}

// ---------------- host launch ----------------
extern "C" void kernel_launch(void* const* d_in, const int* in_sizes, int n_in,
                              void* d_out, int out_size) {
    const float* x    = (const float*)d_in[0];
    const int*   tseq = (const int*)d_in[1];
    const float* emb  = (const float*)d_in[2];
    const float* Wx   = (const float*)d_in[3];
    const float* Wh   = (const float*)d_in[4];
    const float* b1   = (const float*)d_in[5];
    const float* w2   = (const float*)d_in[6];
    const float* b2   = (const float*)d_in[7];
    const float* fcW  = (const float*)d_in[8];
    const float* fcb  = (const float*)d_in[9];
    const float* Wih0 = (const float*)d_in[10];
    const float* Whh0 = (const float*)d_in[11];
    const float* bih0 = (const float*)d_in[12];
    const float* bhh0 = (const float*)d_in[13];
    const float* Wih1 = (const float*)d_in[14];
    const float* Whh1 = (const float*)d_in[15];
    const float* bih1 = (const float*)d_in[16];
    const float* bhh1 = (const float*)d_in[17];
    const float* Wih2 = (const float*)d_in[18];
    const float* Whh2 = (const float*)d_in[19];
    const float* bih2 = (const float*)d_in[20];
    const float* bhh2 = (const float*)d_in[21];
    float* dout = (float*)d_out;

    static cudaStream_t s2 = nullptr;
    static cudaEvent_t evA = nullptr, evB = nullptr, evEnd = nullptr;
    if (!s2) {
        cudaStreamCreateWithFlags(&s2, cudaStreamNonBlocking);
        cudaEventCreateWithFlags(&evA, cudaEventDisableTiming);
        cudaEventCreateWithFlags(&evB, cudaEventDisableTiming);
        cudaEventCreateWithFlags(&evEnd, cudaEventDisableTiming);
    }

    // -------- prologue --------
    // flat: 7,733,248 pack + 1,572,864 x + 49,152 zero + 12,288 emb0 + 1,024 w2
    prolog_combined<<<36596, 256>>>(Wx, Wh, Wih0, Whh0, Wih1, Whh1, Wih2, Whh2, fcW,
                                    x, tseq, emb, w2);
    // x_proj: M=2048, N=1024 (4 nblocks), K=768 (48 chunks), bf16 out
    gemm_v4<false><<<dim3(4, 128, 1), 256>>>(0, EE, 0, 0, nullptr, (long long)HH, 0,
                                             b1, 48);

    // -------- time loop --------
    for (int t = 0; t < TT; t++) {
        // hv = h2 @ Wh : split-K=8
        gemm_v4<false><<<dim3(4, 1, 8), 256>>>(4, 2048, 1, 1, nullptr, (long long)HH,
                                               BB * HH, nullptr, 8);
        hv_reduce<<<64, 256>>>();
        attn_score<<<dim3(16, BB), 256>>>(b2);
        attn_ctx2<<<dim3(12, BB), 256>>>();
        // layer 0: K=2560 split-K=8 (20 chunks each)
        gemm_v4<false><<<dim3(16, 1, 8), 256>>>(1, 2560, 2, 2, nullptr, (long long)4096,
                                                BB * 4096, nullptr, 20);
        lstm_cell<<<64, 256>>>(bih0, bhh0, 0, tseq, emb, t);
        // layer 1: K=2048 split-K=8 (16 chunks each)
        gemm_v4<false><<<dim3(16, 1, 8), 256>>>(2, 2048, 3, 2, nullptr, (long long)4096,
                                                BB * 4096, nullptr, 16);
        lstm_cell<<<64, 256>>>(bih1, bhh1, 1, tseq, emb, t);
        // layer 2
        gemm_v4<false><<<dim3(16, 1, 8), 256>>>(3, 2048, 4, 2, nullptr, (long long)4096,
                                                BB * 4096, nullptr, 16);
        // cell2 overwrites h2 -> must wait for previous step's fc (reads h2)
        if (t > 0) cudaStreamWaitEvent(0, evB, 0);
        lstm_cell<<<64, 256>>>(bih2, bhh2, 2, tseq, emb, t);

        // fork fc + lsm onto side stream (depends only on cell2 of this step)
        cudaEventRecord(evA, 0);
        cudaStreamWaitEvent(s2, evA, 0);
        gemm_v4<true><<<dim3(125, 1, 1), 256, 0, s2>>>(4, 2048, 5, 3,
                                                       dout + (long long)t * VV,
                                                       (long long)TT * VV, 0, fcb, 64);
        cudaEventRecord(evB, s2);
        lsm_kernel<<<BB, 1024, 0, s2>>>(dout, t);
    }
    // join side stream back before capture ends
    cudaEventRecord(evEnd, s2);
    cudaStreamWaitEvent(0, evEnd, 0);
}

// round 14
// speedup vs baseline: 1.4809x; 1.0821x over previous
#include <cuda_runtime.h>
#include <cuda_bf16.h>
#include <cstdint>

#define BB 16
#define SS 128
#define TT 64
#define EE 768
#define HH 1024
#define VV 32000

// ---------------- device scratch (static, no allocation) ----------------
__device__ __nv_bfloat16 g_xbf[BB * SS * EE];
__device__ __nv_bfloat16 g_xprojbf[BB * SS * HH];
__device__ uint4 g_pWx[(HH / 16) * (EE / 16) * 32];
__device__ uint4 g_pWh[(HH / 16) * (HH / 16) * 32];
__device__ uint4 g_pWc0[(4096 / 16) * (2560 / 16) * 32];
__device__ uint4 g_pWc1[(4096 / 16) * (2048 / 16) * 32];
__device__ uint4 g_pWc2[(4096 / 16) * (2048 / 16) * 32];
__device__ uint4 g_pFc[(VV / 16) * (HH / 16) * 32];

__device__ __nv_bfloat16 g_A0[BB * 2560];        // [emb | ctx | h0]
__device__ __nv_bfloat16 g_A1[BB * 2048];        // [h0 | h1_prev]
__device__ __nv_bfloat16 g_A2[2][BB * 2048];     // [h1 | h2], parity-buffered
__device__ float         g_c[3 * BB * HH];
__device__ float         g_hvp[8 * BB * HH];     // hv split-K partials
__device__ __nv_bfloat16 g_w2bf[HH];
__device__ float         g_part[8 * BB * 4096]; // gate split-K partials
__device__ float         g_sc[BB * SS];
__device__ unsigned      g_bcnt;   // grid barrier ticket counter (monotonic)
__device__ unsigned      g_bflag;  // grid barrier epoch flag (monotonic)

// ---------------- prologue (pack + cvt_x + zero + emb0 + w2) ----------------
__global__ void prolog_combined(
    const float* __restrict__ Wx, const float* __restrict__ Wh,
    const float* __restrict__ Wih0, const float* __restrict__ Whh0,
    const float* __restrict__ Wih1, const float* __restrict__ Whh1,
    const float* __restrict__ Wih2, const float* __restrict__ Whh2,
    const float* __restrict__ fcW, const float* __restrict__ x,
    const int* __restrict__ tseq, const float* __restrict__ emb,
    const float* __restrict__ w2) {
    const long long C0 = 98304, C1 = C0 + 131072, C2 = C1 + 1310720,
                    C3 = C2 + 1048576, C4 = C3 + 1048576, C5 = C4 + 4096000;
    long long idx = (long long)blockIdx.x * 256 + threadIdx.x;
    if (idx < C5) {
        uint4* dst; const float *s1, *s2 = nullptr;
        int N, K1, K2 = 0, tr; long long base;
        if (idx < C0)      { dst = g_pWx;  s1 = Wx;   N = HH;   K1 = EE;   tr = 1; base = 0; }
        else if (idx < C1) { dst = g_pWh;  s1 = Wh;   N = HH;   K1 = HH;   tr = 1; base = C0; }
        else if (idx < C2) { dst = g_pWc0; s1 = Wih0; s2 = Whh0; N = 4096; K1 = 1536; K2 = 1024; tr = 0; base = C1; }
        else if (idx < C3) { dst = g_pWc1; s1 = Wih1; s2 = Whh1; N = 4096; K1 = 1024; K2 = 1024; tr = 0; base = C2; }
        else if (idx < C4) { dst = g_pWc2; s1 = Wih2; s2 = Whh2; N = 4096; K1 = 1024; K2 = 1024; tr = 0; base = C3; }
        else               { dst = g_pFc;  s1 = fcW;  N = VV;   K1 = HH;   tr = 0; base = C4; }
        long long li = idx - base;
        int nch = (K1 + K2) >> 4;
        int lane = (int)(li & 31);
        long long tt = li >> 5;
        int ch = (int)(tt % nch);
        int nt = (int)(tt / nch);
        int g = lane >> 2, tig = lane & 3;
        int k = ch * 16 + tig * 2;
        int r0 = nt * 16 + g, r1 = r0 + 8;
        auto ld = [&](int n, int kk) -> float {
            if (kk < K1) return tr ? s1[(long long)kk * N + n] : s1[(long long)n * K1 + kk];
            return s2[(long long)n * HH + (kk - K1)];
        };
        auto p2 = [&](float a, float b) -> unsigned {
            __nv_bfloat162 h = __floats2bfloat162_rn(a, b);
            return *reinterpret_cast<unsigned*>(&h);
        };
        uint4 v;
        v.x = p2(ld(r0, k), ld(r0, k + 1));
        v.y = p2(ld(r0, k + 8), ld(r0, k + 9));
        v.z = p2(ld(r1, k), ld(r1, k + 1));
        v.w = p2(ld(r1, k + 8), ld(r1, k + 9));
        dst[li] = v;
        return;
    }
    long long r = idx - C5;
    if (r < (long long)BB * SS * EE) {
        g_xbf[r] = __float2bfloat16(x[r]);
        return;
    }
    r -= (long long)BB * SS * EE;
    if (r < 3 * BB * HH) {
        g_c[r] = 0.f;
        __nv_bfloat16 z = __float2bfloat16(0.f);
        if (r < BB * HH) {
            int b = (int)(r >> 10), j = (int)(r & 1023);
            g_A0[b * 2560 + 1536 + j] = z;
        }
        if (r < BB * 2048) { g_A1[r] = z; g_A2[0][r] = z; g_A2[1][r] = z; }
        return;
    }
    r -= 3 * BB * HH;
    if (r < BB * EE) {  // emb gather for t=0
        int b = (int)(r / EE), e = (int)(r % EE);
        int tok = tseq[b * TT];
        g_A0[b * 2560 + e] = __float2bfloat16(emb[(long long)tok * EE + e]);
        return;
    }
    r -= BB * EE;
    if (r < HH) g_w2bf[r] = __float2bfloat16(w2[r]);
}

// ---------------- mma + grid barrier helpers ----------------
__device__ __forceinline__ void mma16816(float c[4], uint32_t a0, uint32_t a1, uint32_t a2,
                                         uint32_t a3, uint32_t b0, uint32_t b1) {
    asm volatile(
        "mma.sync.aligned.m16n8k16.row.col.f32.bf16.bf16.f32 "
        "{%0,%1,%2,%3}, {%4,%5,%6,%7}, {%8,%9}, {%0,%1,%2,%3};\n"
        : "+f"(c[0]), "+f"(c[1]), "+f"(c[2]), "+f"(c[3])
        : "r"(a0), "r"(a1), "r"(a2), "r"(a3), "r"(b0), "r"(b1));
}

// epoch-based grid barrier for exactly 128 co-resident blocks; monotonic
// counters survive graph replays (no reset needed).
__device__ __forceinline__ void gridbar() {
    __syncthreads();
    if (threadIdx.x == 0) {
        __threadfence();
        unsigned ticket = atomicAdd(&g_bcnt, 1u);
        unsigned epoch = ticket >> 7;
        if ((ticket & 127u) == 127u) {
            atomicExch(&g_bflag, epoch + 1u);
        } else {
            while (atomicAdd(&g_bflag, 0u) < epoch + 1u) __nanosleep(64);
        }
        __threadfence();
    }
    __syncthreads();
}

// ---------------- GEMM core (M=16, per-block 256 n-cols, one K-slice) ----------
#define SAPITCH 328  // 320 max cols + 8 pad (pitch mod 64 == 8, same as proven layout)

__device__ __forceinline__ void gemm_core(
    char* smraw, const __nv_bfloat16* __restrict__ A, int lda,
    const uint4* __restrict__ B, int nchTot, int nCh, int nt, int z,
    float* __restrict__ C, int ldc) {
    __nv_bfloat16(*s_a)[SAPITCH] = reinterpret_cast<__nv_bfloat16(*)[SAPITCH]>(smraw);
    int w = threadIdx.x >> 5, lane = threadIdx.x & 31;
    int g = lane >> 2, tig = lane & 3;
    int n0 = nt * 256 + w * 32;
    int ch0 = z * nCh;
    int cols4 = nCh * 2;
    for (int idx = threadIdx.x; idx < 16 * cols4; idx += 256) {
        int r = idx / cols4, cc = idx % cols4;
        uint4 v = *reinterpret_cast<const uint4*>(A + (long long)r * lda + ch0 * 16 + cc * 8);
        *reinterpret_cast<uint4*>(&s_a[r][cc * 8]) = v;
    }
    __syncthreads();
    const uint4* bp0 = B + ((long long)(n0 >> 4) * nchTot + ch0) * 32 + lane;
    const uint4* bp1 = bp0 + (long long)nchTot * 32;
    uint32_t sab = (uint32_t)__cvta_generic_to_shared(&s_a[lane & 15][(lane >> 4) * 8]);
    float acc[4][4] = {{0.f}, {0.f}, {0.f}, {0.f}};
#pragma unroll 4
    for (int c = 0; c < nCh; c++) {
        uint4 b0 = __ldg(bp0 + (long long)c * 32);
        uint4 b1 = __ldg(bp1 + (long long)c * 32);
        uint32_t a0, a1, a2, a3;
        asm volatile("ldmatrix.sync.aligned.m8n8.x4.shared.b16 {%0,%1,%2,%3}, [%4];"
                     : "=r"(a0), "=r"(a1), "=r"(a2), "=r"(a3)
                     : "r"(sab + (uint32_t)c * 32));
        mma16816(acc[0], a0, a1, a2, a3, b0.x, b0.y);
        mma16816(acc[1], a0, a1, a2, a3, b0.z, b0.w);
        mma16816(acc[2], a0, a1, a2, a3, b1.x, b1.y);
        mma16816(acc[3], a0, a1, a2, a3, b1.z, b1.w);
    }
    int r0 = g, r1 = g + 8;
#pragma unroll
    for (int q = 0; q < 4; q++) {
        int col = n0 + q * 8 + tig * 2;
        C[(long long)r0 * ldc + col]     = acc[q][0];
        C[(long long)r0 * ldc + col + 1] = acc[q][1];
        C[(long long)r1 * ldc + col]     = acc[q][2];
        C[(long long)r1 * ldc + col + 1] = acc[q][3];
    }
}

// ---------------- LSTM cell phase (128 elements per block) ----------------
__device__ __forceinline__ void cell_phase(
    int layer, int blk, int t, int par,
    const float* __restrict__ bih, const float* __restrict__ bhh,
    const int* __restrict__ tseq, const float* __restrict__ emb) {
    int tid = threadIdx.x;
    if (tid < 128) {
        int idx = blk * 128 + tid;
        int b = idx >> 10, j = idx & 1023;
        float gi = bih[j] + bhh[j];
        float gf = bih[1024 + j] + bhh[1024 + j];
        float gg = bih[2048 + j] + bhh[2048 + j];
        float go = bih[3072 + j] + bhh[3072 + j];
#pragma unroll
        for (int p = 0; p < 8; p++) {
            const float* pp = g_part + p * (BB * 4096) + b * 4096;
            gi += __ldcg(pp + j);             // L2 reads: addresses re-written
            gf += __ldcg(pp + 1024 + j);      // by other blocks between layers
            gg += __ldcg(pp + 2048 + j);
            go += __ldcg(pp + 3072 + j);
        }
        float si = 1.f / (1.f + expf(-gi));
        float sf = 1.f / (1.f + expf(-gf));
        float so = 1.f / (1.f + expf(-go));
        float* cc = g_c + layer * (BB * HH) + idx;
        float cn = sf * (*cc) + si * tanhf(gg);
        *cc = cn;
        __nv_bfloat16 hb = __float2bfloat16(so * tanhf(cn));
        if (layer == 0) {
            g_A1[b * 2048 + j] = hb;                 // gc1 input this step
            g_A0[b * 2560 + 1536 + j] = hb;          // h0 for step t+1
        } else if (layer == 1) {
            g_A2[par][b * 2048 + j] = hb;            // gc2 input this step
            g_A1[b * 2048 + 1024 + j] = hb;          // h1 for step t+1
        } else {
            g_A2[par ^ 1][b * 2048 + 1024 + j] = hb; // h2: hv(t+1), gc2(t+1), fc(t)
        }
    }
    if (layer == 2 && t + 1 < TT && tid < 96) {      // emb gather for step t+1
        int i2 = blk * 96 + tid;
        int be = i2 / EE, e = i2 % EE;
        int tok = tseq[be * TT + t + 1];
        g_A0[be * 2560 + e] = __float2bfloat16(emb[(long long)tok * EE + e]);
    }
}

// ---------------- the whole recurrent step: ONE kernel, 8 grid barriers --------
__global__ __launch_bounds__(256) void step_kernel(
    int t, const float* __restrict__ b2,
    const float* __restrict__ bih0, const float* __restrict__ bhh0,
    const float* __restrict__ bih1, const float* __restrict__ bhh1,
    const float* __restrict__ bih2, const float* __restrict__ bhh2,
    const int* __restrict__ tseq, const float* __restrict__ emb) {
    __shared__ __align__(16) char smraw[16 * SAPITCH * 2];  // 10496 B union
    int blk = blockIdx.x, tid = threadIdx.x;
    int par = t & 1;

    // ---- P0: hv = h2(t-1) @ Wh (32 blocks: 4 n-tiles x 8 z) ----
    if (blk < 32)
        gemm_core(smraw, g_A2[par] + 1024, 2048, g_pWh, HH / 16, 8,
                  blk >> 3, blk & 7, g_hvp + (blk & 7) * (BB * HH), HH);
    gridbar();

    // ---- P1: scores (128 blocks: 16 b x 8 s-chunks; 16 scores each) ----
    {
        float* s_hv = reinterpret_cast<float*>(smraw);  // 1024 floats
        int b = blk >> 3, sch = blk & 7;
#pragma unroll
        for (int k = 0; k < 4; k++) {
            int i = k * 256 + tid;
            float s = 0.f;
#pragma unroll
            for (int p = 0; p < 8; p++) s += g_hvp[p * (BB * HH) + b * HH + i];
            s_hv[i] = s;
        }
        __syncthreads();
        int w = tid >> 5, lane = tid & 31;
        float bb2 = b2[0];
#pragma unroll
        for (int rr = 0; rr < 2; rr++) {
            int s = sch * 16 + w * 2 + rr;
            const __nv_bfloat16* row = g_xprojbf + ((long long)b * SS + s) * HH;
            float sum = 0.f;
#pragma unroll
            for (int it = 0; it < 4; it++) {
                int k0 = it * 256 + lane * 8;
                uint4 xv = *reinterpret_cast<const uint4*>(row + k0);
                uint4 wv = *reinterpret_cast<const uint4*>(g_w2bf + k0);
                const __nv_bfloat162* xp = reinterpret_cast<const __nv_bfloat162*>(&xv);
                const __nv_bfloat162* wp = reinterpret_cast<const __nv_bfloat162*>(&wv);
#pragma unroll
                for (int j = 0; j < 4; j++) {
                    float2 xf = __bfloat1622float2(xp[j]);
                    float2 wf = __bfloat1622float2(wp[j]);
                    float a = xf.x + s_hv[k0 + j * 2];
                    float c = xf.y + s_hv[k0 + j * 2 + 1];
                    sum += (a > 0.f ? a * wf.x : 0.f) + (c > 0.f ? c * wf.y : 0.f);
                }
            }
#pragma unroll
            for (int o = 16; o; o >>= 1) sum += __shfl_xor_sync(0xffffffffu, sum, o);
            if (!lane) g_sc[b * SS + s] = sum + bb2;
        }
    }
    gridbar();

    // ---- P2: log-softmax + context (128 blocks: 16 b x 8 e-chunks of 96) ----
    {
        float* sc = reinterpret_cast<float*>(smraw);       // 128
        float* red = sc + 128;                             // 1
        float* part = sc + 132;                            // 2 x 96
        int b = blk >> 3, ech = blk & 7;
        if (tid < SS) sc[tid] = g_sc[b * SS + tid];
        __syncthreads();
        if (tid < 32) {
            float m = -1e30f;
#pragma unroll
            for (int i = 0; i < 4; i++) m = fmaxf(m, sc[tid + i * 32]);
#pragma unroll
            for (int o = 16; o; o >>= 1) m = fmaxf(m, __shfl_xor_sync(0xffffffffu, m, o));
            float su = 0.f;
#pragma unroll
            for (int i = 0; i < 4; i++) su += expf(sc[tid + i * 32] - m);
#pragma unroll
            for (int o = 16; o; o >>= 1) su += __shfl_xor_sync(0xffffffffu, su, o);
            if (!tid) *red = m + logf(su);
        }
        __syncthreads();
        float lse = *red;
        __syncthreads();
        if (tid < SS) sc[tid] -= lse;
        __syncthreads();
        if (tid < 192) {
            int q = tid / 96, e = tid % 96;
            int eg = ech * 96 + e;
            const __nv_bfloat16* xb = g_xbf + ((long long)b * SS + q * 64) * EE + eg;
            float acc = 0.f;
#pragma unroll 8
            for (int ss = 0; ss < 64; ss++)
                acc += sc[q * 64 + ss] * __bfloat162float(xb[(long long)ss * EE]);
            part[q * 96 + e] = acc;
        }
        __syncthreads();
        if (tid < 96) {
            float a = part[tid] + part[96 + tid];
            g_A0[b * 2560 + EE + ech * 96 + tid] = __float2bfloat16(a);
        }
    }
    gridbar();

    // ---- P3/P4: layer 0 gemm + cell ----
    gemm_core(smraw, g_A0, 2560, g_pWc0, 2560 / 16, 20, blk >> 3, blk & 7,
              g_part + (blk & 7) * (BB * 4096), 4096);
    gridbar();
    cell_phase(0, blk, t, par, bih0, bhh0, tseq, emb);
    gridbar();

    // ---- P5/P6: layer 1 ----
    gemm_core(smraw, g_A1, 2048, g_pWc1, 2048 / 16, 16, blk >> 3, blk & 7,
              g_part + (blk & 7) * (BB * 4096), 4096);
    gridbar();
    cell_phase(1, blk, t, par, bih1, bhh1, tseq, emb);
    gridbar();

    // ---- P7/P8: layer 2 ----
    gemm_core(smraw, g_A2[par], 2048, g_pWc2, 2048 / 16, 16, blk >> 3, blk & 7,
              g_part + (blk & 7) * (BB * 4096), 4096);
    gridbar();
    cell_phase(2, blk, t, par, bih2, bhh2, tseq, emb);
}

// ---------------- standalone GEMM for x_proj + fc ----------------
#define APAD 8
#define AMAXC (64 * 16)

__device__ __forceinline__ const __nv_bfloat16* selA(int t) {
    switch (t) {
        case 0: return g_xbf;
        case 4: return g_A2[0] + 1024;
        default: return g_A2[1] + 1024;
    }
}

// cTag: 0 = g_xprojbf (bf16), 3 = external fp32 (dout)
template <bool EF>
__global__ __launch_bounds__(256) void gemm_v4(
    int aTag, int lda, int bTag, int cTag, float* cExt, long long ldc,
    int partStride, const float* __restrict__ bias, int nCh) {
    __shared__ __nv_bfloat16 s_a[16][AMAXC + APAD];
    const __nv_bfloat16* A = selA(aTag);
    const uint4* B = (bTag == 0) ? g_pWx : g_pFc;
    int nchTot = (bTag == 0) ? EE / 16 : HH / 16;
    int w = threadIdx.x >> 5, lane = threadIdx.x & 31;
    int g = lane >> 2, tig = lane & 3;
    int m0 = blockIdx.y * 16;
    int n0 = blockIdx.x * 256 + w * 32;
    int ch0 = blockIdx.z * nCh;
    {
        int cols4 = nCh * 2;
        for (int idx = threadIdx.x; idx < 16 * cols4; idx += 256) {
            int r = idx / cols4, cc = idx % cols4;
            uint4 v = *reinterpret_cast<const uint4*>(
                A + (long long)(m0 + r) * lda + ch0 * 16 + cc * 8);
            *reinterpret_cast<uint4*>(&s_a[r][cc * 8]) = v;
        }
    }
    __syncthreads();
    const uint4* bp0 = B + ((long long)(n0 >> 4) * nchTot + ch0) * 32 + lane;
    const uint4* bp1 = bp0 + (long long)nchTot * 32;
    uint32_t sab = (uint32_t)__cvta_generic_to_shared(&s_a[lane & 15][(lane >> 4) * 8]);
    float acc[4][4] = {{0.f}, {0.f}, {0.f}, {0.f}};
#pragma unroll 8
    for (int c = 0; c < nCh; c++) {
        uint4 b0 = EF ? __ldcs(bp0 + (long long)c * 32) : __ldg(bp0 + (long long)c * 32);
        uint4 b1 = EF ? __ldcs(bp1 + (long long)c * 32) : __ldg(bp1 + (long long)c * 32);
        uint32_t a0, a1, a2, a3;
        asm volatile("ldmatrix.sync.aligned.m8n8.x4.shared.b16 {%0,%1,%2,%3}, [%4];"
                     : "=r"(a0), "=r"(a1), "=r"(a2), "=r"(a3)
                     : "r"(sab + (uint32_t)c * 32));
        mma16816(acc[0], a0, a1, a2, a3, b0.x, b0.y);
        mma16816(acc[1], a0, a1, a2, a3, b0.z, b0.w);
        mma16816(acc[2], a0, a1, a2, a3, b1.x, b1.y);
        mma16816(acc[3], a0, a1, a2, a3, b1.z, b1.w);
    }
    int r0 = m0 + g, r1 = m0 + g + 8;
    if (cTag == 0) {
        __nv_bfloat16* Cb = g_xprojbf;
#pragma unroll
        for (int q = 0; q < 4; q++) {
            int col = n0 + q * 8 + tig * 2;
            float bv0 = bias[col], bv1 = bias[col + 1];
            Cb[(long long)r0 * ldc + col]     = __float2bfloat16(acc[q][0] + bv0);
            Cb[(long long)r0 * ldc + col + 1] = __float2bfloat16(acc[q][1] + bv1);
            Cb[(long long)r1 * ldc + col]     = __float2bfloat16(acc[q][2] + bv0);
            Cb[(long long)r1 * ldc + col + 1] = __float2bfloat16(acc[q][3] + bv1);
        }
        return;
    }
    float* C = cExt + (long long)blockIdx.z * partStride;
#pragma unroll
    for (int q = 0; q < 4; q++) {
        int col = n0 + q * 8 + tig * 2;
        float bv0 = bias ? bias[col] : 0.f, bv1 = bias ? bias[col + 1] : 0.f;
        C[(long long)r0 * ldc + col]     = acc[q][0] + bv0;
        C[(long long)r0 * ldc + col + 1] = acc[q][1] + bv1;
        C[(long long)r1 * ldc + col]     = acc[q][2] + bv0;
        C[(long long)r1 * ldc + col + 1] = acc[q][3] + bv1;
    }
}

// ---------------- in-place log_softmax over V (float4) ----------------
__global__ __launch_bounds__(1024) void lsm_kernel(float* __restrict__ dout, int t) {
    float4* row = reinterpret_cast<float4*>(dout + (long long)blockIdx.x * TT * VV +
                                            (long long)t * VV);
    const int NV4 = VV / 4;
    __shared__ float sm[32];
    __shared__ float bc;
    int tid = threadIdx.x, lane = tid & 31, wid = tid >> 5;
    float m = -1e30f;
    for (int i = tid; i < NV4; i += 1024) {
        float4 v = row[i];
        m = fmaxf(m, fmaxf(fmaxf(v.x, v.y), fmaxf(v.z, v.w)));
    }
#pragma unroll
    for (int o = 16; o; o >>= 1) m = fmaxf(m, __shfl_xor_sync(0xffffffffu, m, o));
    if (!lane) sm[wid] = m;
    __syncthreads();
    if (tid < 32) {
        float mm = sm[tid];
#pragma unroll
        for (int o = 16; o; o >>= 1) mm = fmaxf(mm, __shfl_xor_sync(0xffffffffu, mm, o));
        if (!tid) bc = mm;
    }
    __syncthreads();
    m = bc;
    float s = 0.f;
    for (int i = tid; i < NV4; i += 1024) {
        float4 v = row[i];
        s += expf(v.x - m) + expf(v.y - m) + expf(v.z - m) + expf(v.w - m);
    }
#pragma unroll
    for (int o = 16; o; o >>= 1) s += __shfl_xor_sync(0xffffffffu, s, o);
    __syncthreads();
    if (!lane) sm[wid] = s;
    __syncthreads();
    if (tid < 32) {
        float ss = sm[tid];
#pragma unroll
        for (int o = 16; o; o >>= 1) ss += __shfl_xor_sync(0xffffffffu, ss, o);
        if (!tid) bc = m + logf(ss);
    }
    __syncthreads();
    float lse = bc;
    for (int i = tid; i < NV4; i += 1024) {
        float4 v = row[i];
        v.x -= lse; v.y -= lse; v.z -= lse; v.w -= lse;
        row[i] = v;
    }
}

// ---------------- host launch ----------------
extern "C" void kernel_launch(void* const* d_in, const int* in_sizes, int n_in,
                              void* d_out, int out_size) {
    const float* x    = (const float*)d_in[0];
    const int*   tseq = (const int*)d_in[1];
    const float* emb  = (const float*)d_in[2];
    const float* Wx   = (const float*)d_in[3];
    const float* Wh   = (const float*)d_in[4];
    const float* b1   = (const float*)d_in[5];
    const float* w2   = (const float*)d_in[6];
    const float* b2   = (const float*)d_in[7];
    const float* fcW  = (const float*)d_in[8];
    const float* fcb  = (const float*)d_in[9];
    const float* Wih0 = (const float*)d_in[10];
    const float* Whh0 = (const float*)d_in[11];
    const float* bih0 = (const float*)d_in[12];
    const float* bhh0 = (const float*)d_in[13];
    const float* Wih1 = (const float*)d_in[14];
    const float* Whh1 = (const float*)d_in[15];
    const float* bih1 = (const float*)d_in[16];
    const float* bhh1 = (const float*)d_in[17];
    const float* Wih2 = (const float*)d_in[18];
    const float* Whh2 = (const float*)d_in[19];
    const float* bih2 = (const float*)d_in[20];
    const float* bhh2 = (const float*)d_in[21];
    float* dout = (float*)d_out;

    static cudaStream_t s2 = nullptr;
    static cudaEvent_t evA = nullptr, evB0 = nullptr, evB1 = nullptr, evEnd = nullptr;
    if (!s2) {
        cudaStreamCreateWithFlags(&s2, cudaStreamNonBlocking);
        cudaEventCreateWithFlags(&evA, cudaEventDisableTiming);
        cudaEventCreateWithFlags(&evB0, cudaEventDisableTiming);
        cudaEventCreateWithFlags(&evB1, cudaEventDisableTiming);
        cudaEventCreateWithFlags(&evEnd, cudaEventDisableTiming);
    }

    // -------- prologue --------
    prolog_combined<<<36596, 256>>>(Wx, Wh, Wih0, Whh0, Wih1, Whh1, Wih2, Whh2, fcW,
                                    x, tseq, emb, w2);
    // x_proj: M=2048, N=1024 (4 nblocks), K=768 (48 chunks), bf16 out
    gemm_v4<false><<<dim3(4, 128, 1), 256>>>(0, EE, 0, 0, nullptr, (long long)HH, 0,
                                             b1, 48);

    // -------- time loop: 1 chain kernel per step + fc/lsm on side stream ------
    for (int t = 0; t < TT; t++) {
        // fc(t-2) read A2[(t+1)&1] h2 slice that cell2(t) will overwrite
        if (t >= 2) cudaStreamWaitEvent(0, (t & 1) ? evB1 : evB0, 0);
        step_kernel<<<128, 256>>>(t, b2, bih0, bhh0, bih1, bhh1, bih2, bhh2, tseq, emb);
        cudaEventRecord(evA, 0);
        cudaStreamWaitEvent(s2, evA, 0);
        // fc reads h2(t) = A2[(t+1)&1] + 1024
        gemm_v4<true><<<dim3(125, 1, 1), 256, 0, s2>>>(4 + ((t + 1) & 1), 2048, 1, 3,
                                                       dout + (long long)t * VV,
                                                       (long long)TT * VV, 0, fcb, 64);
        cudaEventRecord((t & 1) ? evB1 : evB0, s2);
        lsm_kernel<<<BB, 1024, 0, s2>>>(dout, t);
    }
    cudaEventRecord(evEnd, s2);
    cudaStreamWaitEvent(0, evEnd, 0);
}